// round 1
// baseline (speedup 1.0000x reference)
#include <cuda_runtime.h>
#include <cuda_bf16.h>
#include <cstdint>

// ---------------------------------------------------------------------------
// GraphConvolution: out = relu( SpMM_COO(adj, x @ w) + b )
//   x: [N, 256] f32, adj_{row,col}: [E] i32, adj_vals: [E] f32,
//   w: [256, 128] f32, b: [128] f32, out: [N, 128] f32
// Phases:
//   0) cudaMemsetAsync(out, 0)
//   1) SGEMM h = x @ w           (fp32, 128x128x16 register-blocked)
//   2) scatter: out[r] += v * h[c]  (one warp per edge, red.v4.f32)
//   3) out = relu(out + b)
// ---------------------------------------------------------------------------

#define F_IN 256
#define F_OUT 128

// scratch for h = x @ w  (N=100000 rows max)
#define MAX_N 100000
__device__ float g_h[(size_t)MAX_N * F_OUT];

// ---------------- Phase 1: SGEMM  C[M,128] = A[M,256] * B[256,128] ----------
// BM=128, BN=128, BK=16, 256 threads, 8x8 per thread.
__global__ __launch_bounds__(256) void gemm_kernel(
    const float* __restrict__ A,   // [M, 256]
    const float* __restrict__ B,   // [256, 128]
    float* __restrict__ C,         // [M, 128]
    int M)
{
    __shared__ float As[16][128];  // As[k][m]
    __shared__ float Bs[16][128];  // Bs[k][n]

    const int tid = threadIdx.x;
    const int tr = tid >> 4;        // 0..15  (row group)
    const int tc = tid & 15;        // 0..15  (col group)
    const int block_row = blockIdx.x * 128;

    float acc[8][8];
#pragma unroll
    for (int i = 0; i < 8; i++)
#pragma unroll
        for (int j = 0; j < 8; j++) acc[i][j] = 0.f;

    for (int k0 = 0; k0 < F_IN; k0 += 16) {
        // --- load A tile: 128 rows x 16 k = 512 float4, 2 per thread ---
#pragma unroll
        for (int t = 0; t < 2; t++) {
            int v = tid + t * 256;          // 0..511
            int m = v >> 2;                 // 0..127
            int kq = v & 3;                 // which float4 along k
            int grow = block_row + m;
            float4 a;
            if (grow < M)
                a = *reinterpret_cast<const float4*>(A + (size_t)grow * F_IN + k0 + kq * 4);
            else
                a = make_float4(0.f, 0.f, 0.f, 0.f);
            As[kq * 4 + 0][m] = a.x;
            As[kq * 4 + 1][m] = a.y;
            As[kq * 4 + 2][m] = a.z;
            As[kq * 4 + 3][m] = a.w;
        }
        // --- load B tile: 16 k x 128 n = 512 float4, 2 per thread ---
#pragma unroll
        for (int t = 0; t < 2; t++) {
            int v = tid + t * 256;          // 0..511
            int k = v >> 5;                 // 0..15
            int cq = v & 31;                // float4 index along n
            float4 bvec = *reinterpret_cast<const float4*>(B + (size_t)(k0 + k) * F_OUT + cq * 4);
            *reinterpret_cast<float4*>(&Bs[k][cq * 4]) = bvec;
        }
        __syncthreads();

#pragma unroll
        for (int k = 0; k < 16; k++) {
            float4 a0 = *reinterpret_cast<const float4*>(&As[k][tr * 8]);
            float4 a1 = *reinterpret_cast<const float4*>(&As[k][tr * 8 + 4]);
            float4 b0 = *reinterpret_cast<const float4*>(&Bs[k][tc * 8]);
            float4 b1 = *reinterpret_cast<const float4*>(&Bs[k][tc * 8 + 4]);
            float ra[8] = {a0.x, a0.y, a0.z, a0.w, a1.x, a1.y, a1.z, a1.w};
            float rb[8] = {b0.x, b0.y, b0.z, b0.w, b1.x, b1.y, b1.z, b1.w};
#pragma unroll
            for (int i = 0; i < 8; i++)
#pragma unroll
                for (int j = 0; j < 8; j++)
                    acc[i][j] = fmaf(ra[i], rb[j], acc[i][j]);
        }
        __syncthreads();
    }

    // --- store C ---
#pragma unroll
    for (int i = 0; i < 8; i++) {
        int grow = block_row + tr * 8 + i;
        if (grow < M) {
            float4 c0 = make_float4(acc[i][0], acc[i][1], acc[i][2], acc[i][3]);
            float4 c1 = make_float4(acc[i][4], acc[i][5], acc[i][6], acc[i][7]);
            *reinterpret_cast<float4*>(C + (size_t)grow * F_OUT + tc * 8)     = c0;
            *reinterpret_cast<float4*>(C + (size_t)grow * F_OUT + tc * 8 + 4) = c1;
        }
    }
}

// ---------------- Phase 2: COO scatter with vector red ----------------------
// One warp per edge. Lane l handles features [4l, 4l+4).
__global__ __launch_bounds__(256) void scatter_kernel(
    const int*   __restrict__ adj_row,
    const int*   __restrict__ adj_col,
    const float* __restrict__ adj_vals,
    const float* __restrict__ h,     // [N, 128]
    float*       __restrict__ out,   // [N, 128]
    int E)
{
    int gw   = (int)((blockIdx.x * (unsigned)blockDim.x + threadIdx.x) >> 5);
    int lane = threadIdx.x & 31;
    if (gw >= E) return;

    int   r = adj_row[gw];
    int   c = adj_col[gw];
    float v = adj_vals[gw];

    float4 m = *reinterpret_cast<const float4*>(h + (size_t)c * F_OUT + lane * 4);
    m.x *= v; m.y *= v; m.z *= v; m.w *= v;

    float* op = out + (size_t)r * F_OUT + lane * 4;
    asm volatile("red.global.add.v4.f32 [%0], {%1, %2, %3, %4};"
                 :: "l"(op), "f"(m.x), "f"(m.y), "f"(m.z), "f"(m.w)
                 : "memory");
}

// ---------------- Phase 3: bias + relu --------------------------------------
__global__ __launch_bounds__(256) void bias_relu_kernel(
    float* __restrict__ out, const float* __restrict__ b, size_t n_vec4)
{
    size_t i = blockIdx.x * (size_t)blockDim.x + threadIdx.x;
    if (i >= n_vec4) return;
    float4 o = reinterpret_cast<float4*>(out)[i];
    // feature float4 index = i % (F_OUT/4)
    const float4 bv = reinterpret_cast<const float4*>(b)[i & (F_OUT / 4 - 1)];
    o.x = fmaxf(o.x + bv.x, 0.f);
    o.y = fmaxf(o.y + bv.y, 0.f);
    o.z = fmaxf(o.z + bv.z, 0.f);
    o.w = fmaxf(o.w + bv.w, 0.f);
    reinterpret_cast<float4*>(out)[i] = o;
}

// ---------------------------------------------------------------------------
extern "C" void kernel_launch(void* const* d_in, const int* in_sizes, int n_in,
                              void* d_out, int out_size)
{
    const float* x        = (const float*)d_in[0];
    const int*   adj_row  = (const int*)  d_in[1];
    const int*   adj_col  = (const int*)  d_in[2];
    const float* adj_vals = (const float*)d_in[3];
    const float* w        = (const float*)d_in[4];
    const float* b        = (const float*)d_in[5];
    float*       out      = (float*)d_out;

    const int fout = in_sizes[5];               // 128
    const int fin  = in_sizes[4] / fout;        // 256
    const int N    = in_sizes[0] / fin;         // 100000
    const int E    = in_sizes[1];               // 1600000

    float* h;
    cudaGetSymbolAddress((void**)&h, g_h);

    // Phase 0: zero output accumulator
    cudaMemsetAsync(d_out, 0, (size_t)N * fout * sizeof(float), 0);

    // Phase 1: h = x @ w
    dim3 ggrid((N + 127) / 128);
    gemm_kernel<<<ggrid, 256>>>(x, w, h, N);

    // Phase 2: scatter edges (one warp per edge)
    long long total_threads = (long long)E * 32;
    int sblocks = (int)((total_threads + 255) / 256);
    scatter_kernel<<<sblocks, 256>>>(adj_row, adj_col, adj_vals, h, out, E);

    // Phase 3: bias + relu
    size_t n_vec4 = (size_t)N * fout / 4;
    int rblocks = (int)((n_vec4 + 255) / 256);
    bias_relu_kernel<<<rblocks, 256>>>(out, b, n_vec4);
}

// round 3
// speedup vs baseline: 1.3097x; 1.3097x over previous
#include <cuda_runtime.h>
#include <cuda_bf16.h>
#include <cstdint>

// ---------------------------------------------------------------------------
// GraphConvolution: out = relu( SpMM_COO(adj, x @ w) + b )
// Phase 1 GEMM: mma.sync bf16 hi/lo split (baseline PTX, works on compute_103):
//   x@w ~= Xhi@Whi + Xhi@Wlo + Xlo@Whi   (f32 accumulate)
// ---------------------------------------------------------------------------

#define F_IN 256
#define F_OUT 128
#define MAX_N 100000
__device__ float g_h[(size_t)MAX_N * F_OUT];

__device__ __forceinline__ uint32_t smem_to_u32(const void* p) {
    uint32_t a;
    asm("{ .reg .u64 t; cvta.to.shared.u64 t, %1; cvt.u32.u64 %0, t; }" : "=r"(a) : "l"(p));
    return a;
}

// ---- SMEM stage layout (bytes), per double-buffer stage ----
// A tile: 128 rows x 32 k, bf16, row stride 40 elems (80B) -> conflict-free ldmatrix
// B tile: 32 k x 128 n, bf16, row stride 136 elems (272B) -> conflict-free ldmatrix.trans
#define A_ROW_B   80
#define B_ROW_B   272
#define AHI_OFF   0
#define ALO_OFF   10240
#define BHI_OFF   20480
#define BLO_OFF   29184
#define STAGE_SZ  37888
#define SMEM_TOTAL (2 * STAGE_SZ)

#define LDSM_X4(r0, r1, r2, r3, addr) \
    asm volatile("ldmatrix.sync.aligned.m8n8.x4.shared.b16 {%0,%1,%2,%3}, [%4];" \
        : "=r"(r0), "=r"(r1), "=r"(r2), "=r"(r3) : "r"(addr))
#define LDSM_X4_T(r0, r1, r2, r3, addr) \
    asm volatile("ldmatrix.sync.aligned.m8n8.x4.trans.shared.b16 {%0,%1,%2,%3}, [%4];" \
        : "=r"(r0), "=r"(r1), "=r"(r2), "=r"(r3) : "r"(addr))
#define MMA_BF16(d, a, b0, b1) \
    asm volatile("mma.sync.aligned.m16n8k16.row.col.f32.bf16.bf16.f32 " \
        "{%0,%1,%2,%3},{%4,%5,%6,%7},{%8,%9},{%0,%1,%2,%3};" \
        : "+f"((d)[0]), "+f"((d)[1]), "+f"((d)[2]), "+f"((d)[3]) \
        : "r"((a)[0]), "r"((a)[1]), "r"((a)[2]), "r"((a)[3]), "r"(b0), "r"(b1))

__device__ __forceinline__ void split4(float4 v, uint2& hi, uint2& lo) {
    __nv_bfloat16 h0 = __float2bfloat16_rn(v.x);
    __nv_bfloat16 h1 = __float2bfloat16_rn(v.y);
    __nv_bfloat16 h2 = __float2bfloat16_rn(v.z);
    __nv_bfloat16 h3 = __float2bfloat16_rn(v.w);
    __nv_bfloat16 l0 = __float2bfloat16_rn(v.x - __bfloat162float(h0));
    __nv_bfloat16 l1 = __float2bfloat16_rn(v.y - __bfloat162float(h1));
    __nv_bfloat16 l2 = __float2bfloat16_rn(v.z - __bfloat162float(h2));
    __nv_bfloat16 l3 = __float2bfloat16_rn(v.w - __bfloat162float(h3));
    hi.x = ((uint32_t)__bfloat16_as_ushort(h1) << 16) | __bfloat16_as_ushort(h0);
    hi.y = ((uint32_t)__bfloat16_as_ushort(h3) << 16) | __bfloat16_as_ushort(h2);
    lo.x = ((uint32_t)__bfloat16_as_ushort(l1) << 16) | __bfloat16_as_ushort(l0);
    lo.y = ((uint32_t)__bfloat16_as_ushort(l3) << 16) | __bfloat16_as_ushort(l2);
}

// ---------------- Phase 1: mma.sync GEMM  H[M,128] = A[M,256] @ W[256,128] --
// 256 threads = 8 warps: 4 (M) x 2 (N). Warp tile 32x64. BK=32, 8 chunks.
__global__ __launch_bounds__(256, 2) void gemm_mma_kernel(
    const float* __restrict__ A,
    const float* __restrict__ W,
    float* __restrict__ H,
    int M)
{
    extern __shared__ char smem[];
    const uint32_t smem_u32 = smem_to_u32(smem);
    const int tid = threadIdx.x;
    const int lane = tid & 31;
    const int wid = tid >> 5;
    const int wm = wid & 3;          // warp row (0..3)  -> rows wm*32..+32
    const int wn = wid >> 2;         // warp col (0..1)  -> cols wn*64..+64
    const int block_row = blockIdx.x * 128;

    float acc[2][8][4];
#pragma unroll
    for (int mt = 0; mt < 2; mt++)
#pragma unroll
        for (int nt = 0; nt < 8; nt++)
#pragma unroll
            for (int i = 0; i < 4; i++) acc[mt][nt][i] = 0.f;

    // precomputed per-thread shared store offsets (slot s = tid + i*256)
    // A: row = s>>3 (0..127), q = s&7 (float4 along k)
    // B: kr = s>>5 (0..31),   qb = s&31
    float4 areg[4], breg[4];

    auto gload = [&](int c) {
#pragma unroll
        for (int i = 0; i < 4; i++) {
            int s = tid + i * 256;
            int r = s >> 3, q = s & 7;
            int gr = block_row + r;
            areg[i] = (gr < M)
                ? *reinterpret_cast<const float4*>(A + (size_t)gr * F_IN + c * 32 + q * 4)
                : make_float4(0.f, 0.f, 0.f, 0.f);
            int kr = s >> 5, qb = s & 31;
            breg[i] = *reinterpret_cast<const float4*>(W + (size_t)(c * 32 + kr) * F_OUT + qb * 4);
        }
    };
    auto sstore = [&](int buf) {
        char* st = smem + buf * STAGE_SZ;
#pragma unroll
        for (int i = 0; i < 4; i++) {
            int s = tid + i * 256;
            int r = s >> 3, q = s & 7;
            uint2 hi, lo;
            split4(areg[i], hi, lo);
            *reinterpret_cast<uint2*>(st + AHI_OFF + r * A_ROW_B + q * 8) = hi;
            *reinterpret_cast<uint2*>(st + ALO_OFF + r * A_ROW_B + q * 8) = lo;
            int kr = s >> 5, qb = s & 31;
            split4(breg[i], hi, lo);
            *reinterpret_cast<uint2*>(st + BHI_OFF + kr * B_ROW_B + qb * 8) = hi;
            *reinterpret_cast<uint2*>(st + BLO_OFF + kr * B_ROW_B + qb * 8) = lo;
        }
    };

    // A-fragment ldmatrix address pieces (per lane)
    const int a_row_in_tile = lane & 15;           // 0..15
    const int a_k_off = (lane >> 4) * 8;           // 0 or 8
    // B-fragment (trans) address pieces
    const int b_grp = lane >> 3;                   // 0..3
    const int b_lr = lane & 7;
    const int b_k_in = (b_grp & 1) * 8 + b_lr;     // 0..15
    const int b_n_off = (b_grp >> 1) * 8;          // 0 or 8

    auto compute = [&](int buf) {
        const uint32_t st = smem_u32 + (uint32_t)buf * STAGE_SZ;
#pragma unroll
        for (int ks = 0; ks < 2; ks++) {
            uint32_t ah[2][4], al[2][4], bb[4][4];
#pragma unroll
            for (int mt = 0; mt < 2; mt++) {
                int row = wm * 32 + mt * 16 + a_row_in_tile;
                int col = ks * 16 + a_k_off;
                uint32_t ad = st + AHI_OFF + (uint32_t)row * A_ROW_B + (uint32_t)col * 2;
                LDSM_X4(ah[mt][0], ah[mt][1], ah[mt][2], ah[mt][3], ad);
                ad = st + ALO_OFF + (uint32_t)row * A_ROW_B + (uint32_t)col * 2;
                LDSM_X4(al[mt][0], al[mt][1], al[mt][2], al[mt][3], ad);
            }
#pragma unroll
            for (int g = 0; g < 4; g++) {
                int krow = ks * 16 + b_k_in;
                int ncol = wn * 64 + g * 16 + b_n_off;
                uint32_t bd = st + BHI_OFF + (uint32_t)krow * B_ROW_B + (uint32_t)ncol * 2;
                LDSM_X4_T(bb[g][0], bb[g][1], bb[g][2], bb[g][3], bd);
            }
            // hh + lh (share Bhi)
#pragma unroll
            for (int mt = 0; mt < 2; mt++)
#pragma unroll
                for (int nt = 0; nt < 8; nt++) {
                    int g = nt >> 1, p = (nt & 1) * 2;
                    MMA_BF16(acc[mt][nt], ah[mt], bb[g][p], bb[g][p + 1]);
                    MMA_BF16(acc[mt][nt], al[mt], bb[g][p], bb[g][p + 1]);
                }
            // reload B as lo, do hl
#pragma unroll
            for (int g = 0; g < 4; g++) {
                int krow = ks * 16 + b_k_in;
                int ncol = wn * 64 + g * 16 + b_n_off;
                uint32_t bd = st + BLO_OFF + (uint32_t)krow * B_ROW_B + (uint32_t)ncol * 2;
                LDSM_X4_T(bb[g][0], bb[g][1], bb[g][2], bb[g][3], bd);
            }
#pragma unroll
            for (int mt = 0; mt < 2; mt++)
#pragma unroll
                for (int nt = 0; nt < 8; nt++) {
                    int g = nt >> 1, p = (nt & 1) * 2;
                    MMA_BF16(acc[mt][nt], ah[mt], bb[g][p], bb[g][p + 1]);
                }
        }
    };

    // ---- pipelined mainloop: 8 chunks of K=32 ----
    gload(0);
    sstore(0);
    __syncthreads();
#pragma unroll
    for (int c = 0; c < 8; c++) {
        if (c < 7) gload(c + 1);
        compute(c & 1);
        if (c < 7) {
            sstore((c + 1) & 1);
            __syncthreads();
        }
    }

    // ---- epilogue: store acc to H ----
#pragma unroll
    for (int mt = 0; mt < 2; mt++) {
        int row0 = block_row + wm * 32 + mt * 16 + (lane >> 2);
#pragma unroll
        for (int nt = 0; nt < 8; nt++) {
            int col = wn * 64 + nt * 8 + (lane & 3) * 2;
            if (row0 < M)
                *reinterpret_cast<float2*>(H + (size_t)row0 * F_OUT + col) =
                    make_float2(acc[mt][nt][0], acc[mt][nt][1]);
            if (row0 + 8 < M)
                *reinterpret_cast<float2*>(H + (size_t)(row0 + 8) * F_OUT + col) =
                    make_float2(acc[mt][nt][2], acc[mt][nt][3]);
        }
    }
}

// ---------------- Phase 2: COO scatter with vector red ----------------------
__global__ __launch_bounds__(256) void scatter_kernel(
    const int*   __restrict__ adj_row,
    const int*   __restrict__ adj_col,
    const float* __restrict__ adj_vals,
    const float* __restrict__ h,
    float*       __restrict__ out,
    int E)
{
    int gw   = (int)((blockIdx.x * (unsigned)blockDim.x + threadIdx.x) >> 5);
    int lane = threadIdx.x & 31;
    if (gw >= E) return;

    int   r = adj_row[gw];
    int   c = adj_col[gw];
    float v = adj_vals[gw];

    float4 m = *reinterpret_cast<const float4*>(h + (size_t)c * F_OUT + lane * 4);
    m.x *= v; m.y *= v; m.z *= v; m.w *= v;

    float* op = out + (size_t)r * F_OUT + lane * 4;
    asm volatile("red.global.add.v4.f32 [%0], {%1, %2, %3, %4};"
                 :: "l"(op), "f"(m.x), "f"(m.y), "f"(m.z), "f"(m.w)
                 : "memory");
}

// ---------------- Phase 3: bias + relu --------------------------------------
__global__ __launch_bounds__(256) void bias_relu_kernel(
    float* __restrict__ out, const float* __restrict__ b, size_t n_vec4)
{
    size_t i = blockIdx.x * (size_t)blockDim.x + threadIdx.x;
    if (i >= n_vec4) return;
    float4 o = reinterpret_cast<float4*>(out)[i];
    const float4 bv = reinterpret_cast<const float4*>(b)[i & (F_OUT / 4 - 1)];
    o.x = fmaxf(o.x + bv.x, 0.f);
    o.y = fmaxf(o.y + bv.y, 0.f);
    o.z = fmaxf(o.z + bv.z, 0.f);
    o.w = fmaxf(o.w + bv.w, 0.f);
    reinterpret_cast<float4*>(out)[i] = o;
}

// ---------------------------------------------------------------------------
extern "C" void kernel_launch(void* const* d_in, const int* in_sizes, int n_in,
                              void* d_out, int out_size)
{
    const float* x        = (const float*)d_in[0];
    const int*   adj_row  = (const int*)  d_in[1];
    const int*   adj_col  = (const int*)  d_in[2];
    const float* adj_vals = (const float*)d_in[3];
    const float* w        = (const float*)d_in[4];
    const float* b        = (const float*)d_in[5];
    float*       out      = (float*)d_out;

    const int fout = in_sizes[5];               // 128
    const int fin  = in_sizes[4] / fout;        // 256
    const int N    = in_sizes[0] / fin;         // 100000
    const int E    = in_sizes[1];               // 1600000

    float* h;
    cudaGetSymbolAddress((void**)&h, g_h);

    cudaFuncSetAttribute(gemm_mma_kernel, cudaFuncAttributeMaxDynamicSharedMemorySize, SMEM_TOTAL);

    // Phase 0: zero output accumulator
    cudaMemsetAsync(d_out, 0, (size_t)N * fout * sizeof(float), 0);

    // Phase 1: h = x @ w  (mma.sync bf16-split)
    dim3 ggrid((N + 127) / 128);
    gemm_mma_kernel<<<ggrid, 256, SMEM_TOTAL>>>(x, w, h, N);

    // Phase 2: scatter edges (one warp per edge)
    long long total_threads = (long long)E * 32;
    int sblocks = (int)((total_threads + 255) / 256);
    scatter_kernel<<<sblocks, 256>>>(adj_row, adj_col, adj_vals, h, out, E);

    // Phase 3: bias + relu
    size_t n_vec4 = (size_t)N * fout / 4;
    int rblocks = (int)((n_vec4 + 255) / 256);
    bias_relu_kernel<<<rblocks, 256>>>(out, b, n_vec4);
}

// round 4
// speedup vs baseline: 1.9947x; 1.5230x over previous
#include <cuda_runtime.h>
#include <cuda_bf16.h>
#include <cstdint>

// ---------------------------------------------------------------------------
// GraphConvolution: out = relu( SpMM_COO(adj, x @ w) + b )
//  Phase 1: mma.sync bf16 hi/lo split GEMM  (tensor pipe)
//  Phase 2: counting-sort edges to CSR (hist + scan + permute)
//  Phase 3: per-row gather + fused bias/relu  (NO atomics in feature path)
// ---------------------------------------------------------------------------

#define F_IN 256
#define F_OUT 128
#define MAX_N 100000
#define MAX_E 1600000

__device__ float g_h[(size_t)MAX_N * F_OUT];
__device__ int   g_cnt[MAX_N];
__device__ int   g_offs[MAX_N];
__device__ int   g_cursor[MAX_N];
__device__ int   g_bsum[1024];
__device__ int2  g_sorted[MAX_E];

__device__ __forceinline__ uint32_t smem_to_u32(const void* p) {
    uint32_t a;
    asm("{ .reg .u64 t; cvta.to.shared.u64 t, %1; cvt.u32.u64 %0, t; }" : "=r"(a) : "l"(p));
    return a;
}

// ======================= GEMM (unchanged from R3) ===========================
#define A_ROW_B   80
#define B_ROW_B   272
#define AHI_OFF   0
#define ALO_OFF   10240
#define BHI_OFF   20480
#define BLO_OFF   29184
#define STAGE_SZ  37888
#define SMEM_TOTAL (2 * STAGE_SZ)

#define LDSM_X4(r0, r1, r2, r3, addr) \
    asm volatile("ldmatrix.sync.aligned.m8n8.x4.shared.b16 {%0,%1,%2,%3}, [%4];" \
        : "=r"(r0), "=r"(r1), "=r"(r2), "=r"(r3) : "r"(addr))
#define LDSM_X4_T(r0, r1, r2, r3, addr) \
    asm volatile("ldmatrix.sync.aligned.m8n8.x4.trans.shared.b16 {%0,%1,%2,%3}, [%4];" \
        : "=r"(r0), "=r"(r1), "=r"(r2), "=r"(r3) : "r"(addr))
#define MMA_BF16(d, a, b0, b1) \
    asm volatile("mma.sync.aligned.m16n8k16.row.col.f32.bf16.bf16.f32 " \
        "{%0,%1,%2,%3},{%4,%5,%6,%7},{%8,%9},{%0,%1,%2,%3};" \
        : "+f"((d)[0]), "+f"((d)[1]), "+f"((d)[2]), "+f"((d)[3]) \
        : "r"((a)[0]), "r"((a)[1]), "r"((a)[2]), "r"((a)[3]), "r"(b0), "r"(b1))

__device__ __forceinline__ void split4(float4 v, uint2& hi, uint2& lo) {
    __nv_bfloat16 h0 = __float2bfloat16_rn(v.x);
    __nv_bfloat16 h1 = __float2bfloat16_rn(v.y);
    __nv_bfloat16 h2 = __float2bfloat16_rn(v.z);
    __nv_bfloat16 h3 = __float2bfloat16_rn(v.w);
    __nv_bfloat16 l0 = __float2bfloat16_rn(v.x - __bfloat162float(h0));
    __nv_bfloat16 l1 = __float2bfloat16_rn(v.y - __bfloat162float(h1));
    __nv_bfloat16 l2 = __float2bfloat16_rn(v.z - __bfloat162float(h2));
    __nv_bfloat16 l3 = __float2bfloat16_rn(v.w - __bfloat162float(h3));
    hi.x = ((uint32_t)__bfloat16_as_ushort(h1) << 16) | __bfloat16_as_ushort(h0);
    hi.y = ((uint32_t)__bfloat16_as_ushort(h3) << 16) | __bfloat16_as_ushort(h2);
    lo.x = ((uint32_t)__bfloat16_as_ushort(l1) << 16) | __bfloat16_as_ushort(l0);
    lo.y = ((uint32_t)__bfloat16_as_ushort(l3) << 16) | __bfloat16_as_ushort(l2);
}

__global__ __launch_bounds__(256, 2) void gemm_mma_kernel(
    const float* __restrict__ A,
    const float* __restrict__ W,
    float* __restrict__ H,
    int M)
{
    extern __shared__ char smem[];
    const uint32_t smem_u32 = smem_to_u32(smem);
    const int tid = threadIdx.x;
    const int lane = tid & 31;
    const int wid = tid >> 5;
    const int wm = wid & 3;
    const int wn = wid >> 2;
    const int block_row = blockIdx.x * 128;

    float acc[2][8][4];
#pragma unroll
    for (int mt = 0; mt < 2; mt++)
#pragma unroll
        for (int nt = 0; nt < 8; nt++)
#pragma unroll
            for (int i = 0; i < 4; i++) acc[mt][nt][i] = 0.f;

    float4 areg[4], breg[4];

    auto gload = [&](int c) {
#pragma unroll
        for (int i = 0; i < 4; i++) {
            int s = tid + i * 256;
            int r = s >> 3, q = s & 7;
            int gr = block_row + r;
            areg[i] = (gr < M)
                ? *reinterpret_cast<const float4*>(A + (size_t)gr * F_IN + c * 32 + q * 4)
                : make_float4(0.f, 0.f, 0.f, 0.f);
            int kr = s >> 5, qb = s & 31;
            breg[i] = *reinterpret_cast<const float4*>(W + (size_t)(c * 32 + kr) * F_OUT + qb * 4);
        }
    };
    auto sstore = [&](int buf) {
        char* st = smem + buf * STAGE_SZ;
#pragma unroll
        for (int i = 0; i < 4; i++) {
            int s = tid + i * 256;
            int r = s >> 3, q = s & 7;
            uint2 hi, lo;
            split4(areg[i], hi, lo);
            *reinterpret_cast<uint2*>(st + AHI_OFF + r * A_ROW_B + q * 8) = hi;
            *reinterpret_cast<uint2*>(st + ALO_OFF + r * A_ROW_B + q * 8) = lo;
            int kr = s >> 5, qb = s & 31;
            split4(breg[i], hi, lo);
            *reinterpret_cast<uint2*>(st + BHI_OFF + kr * B_ROW_B + qb * 8) = hi;
            *reinterpret_cast<uint2*>(st + BLO_OFF + kr * B_ROW_B + qb * 8) = lo;
        }
    };

    const int a_row_in_tile = lane & 15;
    const int a_k_off = (lane >> 4) * 8;
    const int b_grp = lane >> 3;
    const int b_lr = lane & 7;
    const int b_k_in = (b_grp & 1) * 8 + b_lr;
    const int b_n_off = (b_grp >> 1) * 8;

    auto compute = [&](int buf) {
        const uint32_t st = smem_u32 + (uint32_t)buf * STAGE_SZ;
#pragma unroll
        for (int ks = 0; ks < 2; ks++) {
            uint32_t ah[2][4], al[2][4], bb[4][4];
#pragma unroll
            for (int mt = 0; mt < 2; mt++) {
                int row = wm * 32 + mt * 16 + a_row_in_tile;
                int col = ks * 16 + a_k_off;
                uint32_t ad = st + AHI_OFF + (uint32_t)row * A_ROW_B + (uint32_t)col * 2;
                LDSM_X4(ah[mt][0], ah[mt][1], ah[mt][2], ah[mt][3], ad);
                ad = st + ALO_OFF + (uint32_t)row * A_ROW_B + (uint32_t)col * 2;
                LDSM_X4(al[mt][0], al[mt][1], al[mt][2], al[mt][3], ad);
            }
#pragma unroll
            for (int g = 0; g < 4; g++) {
                int krow = ks * 16 + b_k_in;
                int ncol = wn * 64 + g * 16 + b_n_off;
                uint32_t bd = st + BHI_OFF + (uint32_t)krow * B_ROW_B + (uint32_t)ncol * 2;
                LDSM_X4_T(bb[g][0], bb[g][1], bb[g][2], bb[g][3], bd);
            }
#pragma unroll
            for (int mt = 0; mt < 2; mt++)
#pragma unroll
                for (int nt = 0; nt < 8; nt++) {
                    int g = nt >> 1, p = (nt & 1) * 2;
                    MMA_BF16(acc[mt][nt], ah[mt], bb[g][p], bb[g][p + 1]);
                    MMA_BF16(acc[mt][nt], al[mt], bb[g][p], bb[g][p + 1]);
                }
#pragma unroll
            for (int g = 0; g < 4; g++) {
                int krow = ks * 16 + b_k_in;
                int ncol = wn * 64 + g * 16 + b_n_off;
                uint32_t bd = st + BLO_OFF + (uint32_t)krow * B_ROW_B + (uint32_t)ncol * 2;
                LDSM_X4_T(bb[g][0], bb[g][1], bb[g][2], bb[g][3], bd);
            }
#pragma unroll
            for (int mt = 0; mt < 2; mt++)
#pragma unroll
                for (int nt = 0; nt < 8; nt++) {
                    int g = nt >> 1, p = (nt & 1) * 2;
                    MMA_BF16(acc[mt][nt], ah[mt], bb[g][p], bb[g][p + 1]);
                }
        }
    };

    gload(0);
    sstore(0);
    __syncthreads();
#pragma unroll
    for (int c = 0; c < 8; c++) {
        if (c < 7) gload(c + 1);
        compute(c & 1);
        if (c < 7) {
            sstore((c + 1) & 1);
            __syncthreads();
        }
    }

#pragma unroll
    for (int mt = 0; mt < 2; mt++) {
        int row0 = block_row + wm * 32 + mt * 16 + (lane >> 2);
#pragma unroll
        for (int nt = 0; nt < 8; nt++) {
            int col = wn * 64 + nt * 8 + (lane & 3) * 2;
            if (row0 < M)
                *reinterpret_cast<float2*>(H + (size_t)row0 * F_OUT + col) =
                    make_float2(acc[mt][nt][0], acc[mt][nt][1]);
            if (row0 + 8 < M)
                *reinterpret_cast<float2*>(H + (size_t)(row0 + 8) * F_OUT + col) =
                    make_float2(acc[mt][nt][2], acc[mt][nt][3]);
        }
    }
}

// ======================= CSR build: hist + scan + permute ===================
__global__ __launch_bounds__(256) void hist_kernel(const int* __restrict__ row, int E) {
    int e = blockIdx.x * 256 + threadIdx.x;
    if (e < E) atomicAdd(&g_cnt[row[e]], 1);
}

// block-level exclusive scan of 1024 elements
__device__ __forceinline__ int block_excl_scan(int v, int tid, int* total) {
    const unsigned full = 0xffffffffu;
    int lane = tid & 31, wid = tid >> 5;
    int x = v;
#pragma unroll
    for (int d = 1; d < 32; d <<= 1) {
        int y = __shfl_up_sync(full, x, d);
        if (lane >= d) x += y;
    }
    __shared__ int wsum[32];
    if (lane == 31) wsum[wid] = x;
    __syncthreads();
    if (wid == 0) {
        int s = wsum[lane];
#pragma unroll
        for (int d = 1; d < 32; d <<= 1) {
            int y = __shfl_up_sync(full, s, d);
            if (lane >= d) s += y;
        }
        wsum[lane] = s;
    }
    __syncthreads();
    int woff = (wid > 0) ? wsum[wid - 1] : 0;
    if (total) *total = wsum[31];
    return woff + x - v;   // exclusive
}

__global__ __launch_bounds__(1024) void scan1_kernel(int n, int nb) {
    int i = blockIdx.x * 1024 + threadIdx.x;
    int v = (i < n) ? g_cnt[i] : 0;
    int total;
    int excl = block_excl_scan(v, threadIdx.x, &total);
    if (i < n) g_offs[i] = excl;
    if (threadIdx.x == 0) g_bsum[blockIdx.x] = total;
}

__global__ __launch_bounds__(1024) void scan2_kernel(int nb) {
    int v = (threadIdx.x < nb) ? g_bsum[threadIdx.x] : 0;
    int excl = block_excl_scan(v, threadIdx.x, nullptr);
    if (threadIdx.x < nb) g_bsum[threadIdx.x] = excl;
}

__global__ __launch_bounds__(1024) void scan3_kernel(int n) {
    int i = blockIdx.x * 1024 + threadIdx.x;
    if (i < n) {
        int o = g_offs[i] + g_bsum[blockIdx.x];
        g_offs[i] = o;
        g_cursor[i] = o;
    }
}

__global__ __launch_bounds__(256) void permute_kernel(
    const int* __restrict__ row, const int* __restrict__ col,
    const float* __restrict__ val, int E)
{
    int e = blockIdx.x * 256 + threadIdx.x;
    if (e >= E) return;
    int r = row[e];
    int p = atomicAdd(&g_cursor[r], 1);
    g_sorted[p] = make_int2(col[e], __float_as_int(val[e]));
}

// ======================= Gather + fused bias/relu ===========================
// One warp per output row; lane owns 4 contiguous features.
__global__ __launch_bounds__(256) void gather_kernel(
    const float* __restrict__ h, const float* __restrict__ b,
    float* __restrict__ out, int N)
{
    int row = (int)((blockIdx.x * 256u + threadIdx.x) >> 5);
    int lane = threadIdx.x & 31;
    if (row >= N) return;

    int start = g_offs[row];
    int deg   = g_cnt[row];

    float4 acc = make_float4(0.f, 0.f, 0.f, 0.f);
    const unsigned full = 0xffffffffu;

    for (int base = 0; base < deg; base += 32) {
        int nn = deg - base;
        if (nn > 32) nn = 32;
        int2 cv = make_int2(0, 0);
        if (lane < nn) cv = g_sorted[start + base + lane];
        for (int j = 0; j < nn; j++) {
            int   c = __shfl_sync(full, cv.x, j);
            float v = __int_as_float(__shfl_sync(full, cv.y, j));
            const float4 m = *reinterpret_cast<const float4*>(h + (size_t)c * F_OUT + lane * 4);
            acc.x = fmaf(v, m.x, acc.x);
            acc.y = fmaf(v, m.y, acc.y);
            acc.z = fmaf(v, m.z, acc.z);
            acc.w = fmaf(v, m.w, acc.w);
        }
    }

    const float4 bv = *reinterpret_cast<const float4*>(b + lane * 4);
    acc.x = fmaxf(acc.x + bv.x, 0.f);
    acc.y = fmaxf(acc.y + bv.y, 0.f);
    acc.z = fmaxf(acc.z + bv.z, 0.f);
    acc.w = fmaxf(acc.w + bv.w, 0.f);
    *reinterpret_cast<float4*>(out + (size_t)row * F_OUT + lane * 4) = acc;
}

// ---------------------------------------------------------------------------
extern "C" void kernel_launch(void* const* d_in, const int* in_sizes, int n_in,
                              void* d_out, int out_size)
{
    const float* x        = (const float*)d_in[0];
    const int*   adj_row  = (const int*)  d_in[1];
    const int*   adj_col  = (const int*)  d_in[2];
    const float* adj_vals = (const float*)d_in[3];
    const float* w        = (const float*)d_in[4];
    const float* b        = (const float*)d_in[5];
    float*       out      = (float*)d_out;

    const int fout = in_sizes[5];               // 128
    const int fin  = in_sizes[4] / fout;        // 256
    const int N    = in_sizes[0] / fin;         // 100000
    const int E    = in_sizes[1];               // 1600000

    float* h;
    cudaGetSymbolAddress((void**)&h, g_h);
    int* cnt;
    cudaGetSymbolAddress((void**)&cnt, g_cnt);

    cudaFuncSetAttribute(gemm_mma_kernel, cudaFuncAttributeMaxDynamicSharedMemorySize, SMEM_TOTAL);

    const int NB = (N + 1023) / 1024;

    // --- CSR build ---
    cudaMemsetAsync(cnt, 0, (size_t)N * sizeof(int), 0);
    hist_kernel<<<(E + 255) / 256, 256>>>(adj_row, E);
    scan1_kernel<<<NB, 1024>>>(N, NB);
    scan2_kernel<<<1, 1024>>>(NB);
    scan3_kernel<<<NB, 1024>>>(N);
    permute_kernel<<<(E + 255) / 256, 256>>>(adj_row, adj_col, adj_vals, E);

    // --- GEMM h = x @ w ---
    gemm_mma_kernel<<<(N + 127) / 128, 256, SMEM_TOTAL>>>(x, w, h, N);

    // --- Gather + bias + relu ---
    gather_kernel<<<(N * 32 + 255) / 256, 256>>>(h, b, out, N);
}

// round 5
// speedup vs baseline: 2.0208x; 1.0131x over previous
#include <cuda_runtime.h>
#include <cuda_bf16.h>
#include <cstdint>

// ---------------------------------------------------------------------------
// GraphConvolution: out = relu( SpMM_COO(adj, x @ w) + b )
//  Two-stream pipelined:
//    s0: gemm_half0 -> gemm_half1 -> (wait csr) gather_half1
//    s1: CSR build (hist/scan/permute) -> (wait gemm_half0) gather_half0
// ---------------------------------------------------------------------------

#define F_IN 256
#define F_OUT 128
#define BN 64
#define MAX_N 100000
#define MAX_E 1600000

__device__ float g_h[(size_t)MAX_N * F_OUT];
__device__ int   g_cnt[MAX_N];
__device__ int   g_offs[MAX_N];
__device__ int   g_cursor[MAX_N];
__device__ int   g_bsum[1024];
__device__ int2  g_sorted[MAX_E];

__device__ __forceinline__ uint32_t smem_to_u32(const void* p) {
    uint32_t a;
    asm("{ .reg .u64 t; cvta.to.shared.u64 t, %1; cvt.u32.u64 %0, t; }" : "=r"(a) : "l"(p));
    return a;
}

// ======================= half-N GEMM (BM=128, BN=64, BK=32) ================
#define A_ROW_B   80
#define B_ROW_B   144
#define AHI_OFF   0
#define ALO_OFF   10240
#define BHI_OFF   20480
#define BLO_OFF   25088
#define STAGE_SZ  29696
#define SMEM_TOTAL (2 * STAGE_SZ)

#define LDSM_X4(r0, r1, r2, r3, addr) \
    asm volatile("ldmatrix.sync.aligned.m8n8.x4.shared.b16 {%0,%1,%2,%3}, [%4];" \
        : "=r"(r0), "=r"(r1), "=r"(r2), "=r"(r3) : "r"(addr))
#define LDSM_X4_T(r0, r1, r2, r3, addr) \
    asm volatile("ldmatrix.sync.aligned.m8n8.x4.trans.shared.b16 {%0,%1,%2,%3}, [%4];" \
        : "=r"(r0), "=r"(r1), "=r"(r2), "=r"(r3) : "r"(addr))
#define MMA_BF16(d, a, b0, b1) \
    asm volatile("mma.sync.aligned.m16n8k16.row.col.f32.bf16.bf16.f32 " \
        "{%0,%1,%2,%3},{%4,%5,%6,%7},{%8,%9},{%0,%1,%2,%3};" \
        : "+f"((d)[0]), "+f"((d)[1]), "+f"((d)[2]), "+f"((d)[3]) \
        : "r"((a)[0]), "r"((a)[1]), "r"((a)[2]), "r"((a)[3]), "r"(b0), "r"(b1))

__device__ __forceinline__ void split4(float4 v, uint2& hi, uint2& lo) {
    __nv_bfloat16 h0 = __float2bfloat16_rn(v.x);
    __nv_bfloat16 h1 = __float2bfloat16_rn(v.y);
    __nv_bfloat16 h2 = __float2bfloat16_rn(v.z);
    __nv_bfloat16 h3 = __float2bfloat16_rn(v.w);
    __nv_bfloat16 l0 = __float2bfloat16_rn(v.x - __bfloat162float(h0));
    __nv_bfloat16 l1 = __float2bfloat16_rn(v.y - __bfloat162float(h1));
    __nv_bfloat16 l2 = __float2bfloat16_rn(v.z - __bfloat162float(h2));
    __nv_bfloat16 l3 = __float2bfloat16_rn(v.w - __bfloat162float(h3));
    hi.x = ((uint32_t)__bfloat16_as_ushort(h1) << 16) | __bfloat16_as_ushort(h0);
    hi.y = ((uint32_t)__bfloat16_as_ushort(h3) << 16) | __bfloat16_as_ushort(h2);
    lo.x = ((uint32_t)__bfloat16_as_ushort(l1) << 16) | __bfloat16_as_ushort(l0);
    lo.y = ((uint32_t)__bfloat16_as_ushort(l3) << 16) | __bfloat16_as_ushort(l2);
}

// 256 threads = 8 warps: 4 (M) x 2 (N). Warp tile 32x32.
__global__ __launch_bounds__(256, 2) void gemm_half_kernel(
    const float* __restrict__ A,
    const float* __restrict__ W,
    float* __restrict__ H,
    int M, int noff)
{
    extern __shared__ char smem[];
    const uint32_t smem_u32 = smem_to_u32(smem);
    const int tid = threadIdx.x;
    const int lane = tid & 31;
    const int wid = tid >> 5;
    const int wm = wid & 3;
    const int wn = wid >> 2;
    const int block_row = blockIdx.x * 128;

    float acc[2][4][4];
#pragma unroll
    for (int mt = 0; mt < 2; mt++)
#pragma unroll
        for (int nt = 0; nt < 4; nt++)
#pragma unroll
            for (int i = 0; i < 4; i++) acc[mt][nt][i] = 0.f;

    float4 areg[4], breg[2];

    auto gload = [&](int c) {
#pragma unroll
        for (int i = 0; i < 4; i++) {
            int s = tid + i * 256;
            int r = s >> 3, q = s & 7;
            int gr = block_row + r;
            areg[i] = (gr < M)
                ? *reinterpret_cast<const float4*>(A + (size_t)gr * F_IN + c * 32 + q * 4)
                : make_float4(0.f, 0.f, 0.f, 0.f);
        }
#pragma unroll
        for (int i = 0; i < 2; i++) {
            int s = tid + i * 256;
            int kr = s >> 4, qb = s & 15;
            breg[i] = *reinterpret_cast<const float4*>(W + (size_t)(c * 32 + kr) * F_OUT + noff + qb * 4);
        }
    };
    auto sstore = [&](int buf) {
        char* st = smem + buf * STAGE_SZ;
#pragma unroll
        for (int i = 0; i < 4; i++) {
            int s = tid + i * 256;
            int r = s >> 3, q = s & 7;
            uint2 hi, lo;
            split4(areg[i], hi, lo);
            *reinterpret_cast<uint2*>(st + AHI_OFF + r * A_ROW_B + q * 8) = hi;
            *reinterpret_cast<uint2*>(st + ALO_OFF + r * A_ROW_B + q * 8) = lo;
        }
#pragma unroll
        for (int i = 0; i < 2; i++) {
            int s = tid + i * 256;
            int kr = s >> 4, qb = s & 15;
            uint2 hi, lo;
            split4(breg[i], hi, lo);
            *reinterpret_cast<uint2*>(st + BHI_OFF + kr * B_ROW_B + qb * 8) = hi;
            *reinterpret_cast<uint2*>(st + BLO_OFF + kr * B_ROW_B + qb * 8) = lo;
        }
    };

    const int a_row_in_tile = lane & 15;
    const int a_k_off = (lane >> 4) * 8;
    const int b_grp = lane >> 3;
    const int b_lr = lane & 7;
    const int b_k_in = (b_grp & 1) * 8 + b_lr;
    const int b_n_off = (b_grp >> 1) * 8;

    auto compute = [&](int buf) {
        const uint32_t st = smem_u32 + (uint32_t)buf * STAGE_SZ;
#pragma unroll
        for (int ks = 0; ks < 2; ks++) {
            uint32_t ah[2][4], al[2][4], bb[2][4];
#pragma unroll
            for (int mt = 0; mt < 2; mt++) {
                int row = wm * 32 + mt * 16 + a_row_in_tile;
                int col = ks * 16 + a_k_off;
                uint32_t ad = st + AHI_OFF + (uint32_t)row * A_ROW_B + (uint32_t)col * 2;
                LDSM_X4(ah[mt][0], ah[mt][1], ah[mt][2], ah[mt][3], ad);
                ad = st + ALO_OFF + (uint32_t)row * A_ROW_B + (uint32_t)col * 2;
                LDSM_X4(al[mt][0], al[mt][1], al[mt][2], al[mt][3], ad);
            }
#pragma unroll
            for (int g = 0; g < 2; g++) {
                int krow = ks * 16 + b_k_in;
                int ncol = wn * 32 + g * 16 + b_n_off;
                uint32_t bd = st + BHI_OFF + (uint32_t)krow * B_ROW_B + (uint32_t)ncol * 2;
                LDSM_X4_T(bb[g][0], bb[g][1], bb[g][2], bb[g][3], bd);
            }
#pragma unroll
            for (int mt = 0; mt < 2; mt++)
#pragma unroll
                for (int nt = 0; nt < 4; nt++) {
                    int g = nt >> 1, p = (nt & 1) * 2;
                    MMA_BF16(acc[mt][nt], ah[mt], bb[g][p], bb[g][p + 1]);
                    MMA_BF16(acc[mt][nt], al[mt], bb[g][p], bb[g][p + 1]);
                }
#pragma unroll
            for (int g = 0; g < 2; g++) {
                int krow = ks * 16 + b_k_in;
                int ncol = wn * 32 + g * 16 + b_n_off;
                uint32_t bd = st + BLO_OFF + (uint32_t)krow * B_ROW_B + (uint32_t)ncol * 2;
                LDSM_X4_T(bb[g][0], bb[g][1], bb[g][2], bb[g][3], bd);
            }
#pragma unroll
            for (int mt = 0; mt < 2; mt++)
#pragma unroll
                for (int nt = 0; nt < 4; nt++) {
                    int g = nt >> 1, p = (nt & 1) * 2;
                    MMA_BF16(acc[mt][nt], ah[mt], bb[g][p], bb[g][p + 1]);
                }
        }
    };

    gload(0);
    sstore(0);
    __syncthreads();
#pragma unroll
    for (int c = 0; c < 8; c++) {
        if (c < 7) gload(c + 1);
        compute(c & 1);
        if (c < 7) {
            sstore((c + 1) & 1);
            __syncthreads();
        }
    }

#pragma unroll
    for (int mt = 0; mt < 2; mt++) {
        int row0 = block_row + wm * 32 + mt * 16 + (lane >> 2);
#pragma unroll
        for (int nt = 0; nt < 4; nt++) {
            int col = noff + wn * 32 + nt * 8 + (lane & 3) * 2;
            if (row0 < M)
                *reinterpret_cast<float2*>(H + (size_t)row0 * F_OUT + col) =
                    make_float2(acc[mt][nt][0], acc[mt][nt][1]);
            if (row0 + 8 < M)
                *reinterpret_cast<float2*>(H + (size_t)(row0 + 8) * F_OUT + col) =
                    make_float2(acc[mt][nt][2], acc[mt][nt][3]);
        }
    }
}

// ======================= CSR build: hist + scan + permute ===================
__global__ __launch_bounds__(256) void hist_kernel(const int* __restrict__ row, int E) {
    int e = blockIdx.x * 256 + threadIdx.x;
    if (e < E) atomicAdd(&g_cnt[row[e]], 1);
}

__device__ __forceinline__ int block_excl_scan(int v, int tid, int* total) {
    const unsigned full = 0xffffffffu;
    int lane = tid & 31, wid = tid >> 5;
    int x = v;
#pragma unroll
    for (int d = 1; d < 32; d <<= 1) {
        int y = __shfl_up_sync(full, x, d);
        if (lane >= d) x += y;
    }
    __shared__ int wsum[32];
    if (lane == 31) wsum[wid] = x;
    __syncthreads();
    if (wid == 0) {
        int s = wsum[lane];
#pragma unroll
        for (int d = 1; d < 32; d <<= 1) {
            int y = __shfl_up_sync(full, s, d);
            if (lane >= d) s += y;
        }
        wsum[lane] = s;
    }
    __syncthreads();
    int woff = (wid > 0) ? wsum[wid - 1] : 0;
    if (total) *total = wsum[31];
    return woff + x - v;
}

__global__ __launch_bounds__(1024) void scan1_kernel(int n, int nb) {
    int i = blockIdx.x * 1024 + threadIdx.x;
    int v = (i < n) ? g_cnt[i] : 0;
    int total;
    int excl = block_excl_scan(v, threadIdx.x, &total);
    if (i < n) g_offs[i] = excl;
    if (threadIdx.x == 0) g_bsum[blockIdx.x] = total;
}

__global__ __launch_bounds__(1024) void scan2_kernel(int nb) {
    int v = (threadIdx.x < nb) ? g_bsum[threadIdx.x] : 0;
    int excl = block_excl_scan(v, threadIdx.x, nullptr);
    if (threadIdx.x < nb) g_bsum[threadIdx.x] = excl;
}

__global__ __launch_bounds__(1024) void scan3_kernel(int n) {
    int i = blockIdx.x * 1024 + threadIdx.x;
    if (i < n) {
        int o = g_offs[i] + g_bsum[blockIdx.x];
        g_offs[i] = o;
        g_cursor[i] = o;
    }
}

__global__ __launch_bounds__(256) void permute_kernel(
    const int* __restrict__ row, const int* __restrict__ col,
    const float* __restrict__ val, int E)
{
    int e = blockIdx.x * 256 + threadIdx.x;
    if (e >= E) return;
    int r = row[e];
    int p = atomicAdd(&g_cursor[r], 1);
    g_sorted[p] = make_int2(col[e], __float_as_int(val[e]));
}

// ======================= Gather half (64 features) + bias/relu ==============
// One warp per row; lane owns 2 contiguous features in [noff, noff+64).
__global__ __launch_bounds__(256) void gather_half_kernel(
    const float* __restrict__ h, const float* __restrict__ b,
    float* __restrict__ out, int N, int noff)
{
    int row = (int)((blockIdx.x * 256u + threadIdx.x) >> 5);
    int lane = threadIdx.x & 31;
    if (row >= N) return;

    int start = g_offs[row];
    int deg   = g_cnt[row];

    float2 acc = make_float2(0.f, 0.f);
    const unsigned full = 0xffffffffu;

    for (int base = 0; base < deg; base += 32) {
        int nn = deg - base;
        if (nn > 32) nn = 32;
        int2 cv = make_int2(0, 0);
        if (lane < nn) cv = g_sorted[start + base + lane];
        for (int j = 0; j < nn; j++) {
            int   c = __shfl_sync(full, cv.x, j);
            float v = __int_as_float(__shfl_sync(full, cv.y, j));
            const float2 m = *reinterpret_cast<const float2*>(h + (size_t)c * F_OUT + noff + lane * 2);
            acc.x = fmaf(v, m.x, acc.x);
            acc.y = fmaf(v, m.y, acc.y);
        }
    }

    const float2 bv = *reinterpret_cast<const float2*>(b + noff + lane * 2);
    acc.x = fmaxf(acc.x + bv.x, 0.f);
    acc.y = fmaxf(acc.y + bv.y, 0.f);
    *reinterpret_cast<float2*>(out + (size_t)row * F_OUT + noff + lane * 2) = acc;
}

// ---------------------------------------------------------------------------
extern "C" void kernel_launch(void* const* d_in, const int* in_sizes, int n_in,
                              void* d_out, int out_size)
{
    const float* x        = (const float*)d_in[0];
    const int*   adj_row  = (const int*)  d_in[1];
    const int*   adj_col  = (const int*)  d_in[2];
    const float* adj_vals = (const float*)d_in[3];
    const float* w        = (const float*)d_in[4];
    const float* b        = (const float*)d_in[5];
    float*       out      = (float*)d_out;

    const int fout = in_sizes[5];               // 128
    const int fin  = in_sizes[4] / fout;        // 256
    const int N    = in_sizes[0] / fin;         // 100000
    const int E    = in_sizes[1];               // 1600000

    float* h;
    cudaGetSymbolAddress((void**)&h, g_h);
    int* cnt;
    cudaGetSymbolAddress((void**)&cnt, g_cnt);

    static cudaStream_t s1 = nullptr;
    static cudaEvent_t ev_root, ev_csr, ev_g0, ev_s1;
    if (!s1) {
        cudaStreamCreateWithFlags(&s1, cudaStreamNonBlocking);
        cudaEventCreateWithFlags(&ev_root, cudaEventDisableTiming);
        cudaEventCreateWithFlags(&ev_csr,  cudaEventDisableTiming);
        cudaEventCreateWithFlags(&ev_g0,   cudaEventDisableTiming);
        cudaEventCreateWithFlags(&ev_s1,   cudaEventDisableTiming);
        cudaFuncSetAttribute(gemm_half_kernel, cudaFuncAttributeMaxDynamicSharedMemorySize, SMEM_TOTAL);
    }

    const int NB = (N + 1023) / 1024;
    const int ggrid = (N + 127) / 128;
    const int gagrid = (int)(((long long)N * 32 + 255) / 256);

    // fork s1 off the capture stream
    cudaEventRecord(ev_root, 0);
    cudaStreamWaitEvent(s1, ev_root, 0);

    // --- s1: CSR build ---
    cudaMemsetAsync(cnt, 0, (size_t)N * sizeof(int), s1);
    hist_kernel<<<(E + 255) / 256, 256, 0, s1>>>(adj_row, E);
    scan1_kernel<<<NB, 1024, 0, s1>>>(N, NB);
    scan2_kernel<<<1, 1024, 0, s1>>>(NB);
    scan3_kernel<<<NB, 1024, 0, s1>>>(N);
    permute_kernel<<<(E + 255) / 256, 256, 0, s1>>>(adj_row, adj_col, adj_vals, E);
    cudaEventRecord(ev_csr, s1);

    // --- s0: GEMM halves ---
    gemm_half_kernel<<<ggrid, 256, SMEM_TOTAL, 0>>>(x, w, h, N, 0);
    cudaEventRecord(ev_g0, 0);
    gemm_half_kernel<<<ggrid, 256, SMEM_TOTAL, 0>>>(x, w, h, N, BN);

    // --- s1: gather half 0 (needs CSR [in-stream] + gemm half 0) ---
    cudaStreamWaitEvent(s1, ev_g0, 0);
    gather_half_kernel<<<gagrid, 256, 0, s1>>>(h, b, out, N, 0);
    cudaEventRecord(ev_s1, s1);

    // --- s0: gather half 1 (needs gemm half 1 [in-stream] + CSR) ---
    cudaStreamWaitEvent(0, ev_csr, 0);
    gather_half_kernel<<<gagrid, 256, 0, 0>>>(h, b, out, N, BN);

    // join
    cudaStreamWaitEvent(0, ev_s1, 0);
}

// round 6
// speedup vs baseline: 2.4540x; 1.2144x over previous
#include <cuda_runtime.h>
#include <cuda_bf16.h>
#include <cuda_fp16.h>
#include <cstdint>

// ---------------------------------------------------------------------------
// GraphConvolution: out = relu( SpMM_COO(adj, x @ w) + b )
//  s1: CSR build (hist/scan/permute)      [hidden under GEMM]
//  s0: full bf16-split mma.sync GEMM -> h stored as fp16
//  s0: gather (fp16 h, fp32 accum) + fused bias/relu     [waits CSR]
// ---------------------------------------------------------------------------

#define F_IN 256
#define F_OUT 128
#define MAX_N 100000
#define MAX_E 1600000

__device__ __half g_h[(size_t)MAX_N * F_OUT];
__device__ int   g_cnt[MAX_N];
__device__ int   g_offs[MAX_N];
__device__ int   g_cursor[MAX_N];
__device__ int   g_bsum[1024];
__device__ int2  g_sorted[MAX_E];

__device__ __forceinline__ uint32_t smem_to_u32(const void* p) {
    uint32_t a;
    asm("{ .reg .u64 t; cvta.to.shared.u64 t, %1; cvt.u32.u64 %0, t; }" : "=r"(a) : "l"(p));
    return a;
}

// ======================= full GEMM (BM=128, BN=128, BK=32) ==================
#define A_ROW_B   80
#define B_ROW_B   272
#define AHI_OFF   0
#define ALO_OFF   10240
#define BHI_OFF   20480
#define BLO_OFF   29184
#define STAGE_SZ  37888
#define SMEM_TOTAL (2 * STAGE_SZ)

#define LDSM_X4(r0, r1, r2, r3, addr) \
    asm volatile("ldmatrix.sync.aligned.m8n8.x4.shared.b16 {%0,%1,%2,%3}, [%4];" \
        : "=r"(r0), "=r"(r1), "=r"(r2), "=r"(r3) : "r"(addr))
#define LDSM_X4_T(r0, r1, r2, r3, addr) \
    asm volatile("ldmatrix.sync.aligned.m8n8.x4.trans.shared.b16 {%0,%1,%2,%3}, [%4];" \
        : "=r"(r0), "=r"(r1), "=r"(r2), "=r"(r3) : "r"(addr))
#define MMA_BF16(d, a, b0, b1) \
    asm volatile("mma.sync.aligned.m16n8k16.row.col.f32.bf16.bf16.f32 " \
        "{%0,%1,%2,%3},{%4,%5,%6,%7},{%8,%9},{%0,%1,%2,%3};" \
        : "+f"((d)[0]), "+f"((d)[1]), "+f"((d)[2]), "+f"((d)[3]) \
        : "r"((a)[0]), "r"((a)[1]), "r"((a)[2]), "r"((a)[3]), "r"(b0), "r"(b1))

__device__ __forceinline__ void split4(float4 v, uint2& hi, uint2& lo) {
    __nv_bfloat16 h0 = __float2bfloat16_rn(v.x);
    __nv_bfloat16 h1 = __float2bfloat16_rn(v.y);
    __nv_bfloat16 h2 = __float2bfloat16_rn(v.z);
    __nv_bfloat16 h3 = __float2bfloat16_rn(v.w);
    __nv_bfloat16 l0 = __float2bfloat16_rn(v.x - __bfloat162float(h0));
    __nv_bfloat16 l1 = __float2bfloat16_rn(v.y - __bfloat162float(h1));
    __nv_bfloat16 l2 = __float2bfloat16_rn(v.z - __bfloat162float(h2));
    __nv_bfloat16 l3 = __float2bfloat16_rn(v.w - __bfloat162float(h3));
    hi.x = ((uint32_t)__bfloat16_as_ushort(h1) << 16) | __bfloat16_as_ushort(h0);
    hi.y = ((uint32_t)__bfloat16_as_ushort(h3) << 16) | __bfloat16_as_ushort(h2);
    lo.x = ((uint32_t)__bfloat16_as_ushort(l1) << 16) | __bfloat16_as_ushort(l0);
    lo.y = ((uint32_t)__bfloat16_as_ushort(l3) << 16) | __bfloat16_as_ushort(l2);
}

__global__ __launch_bounds__(256, 2) void gemm_mma_kernel(
    const float* __restrict__ A,
    const float* __restrict__ W,
    __half* __restrict__ H,
    int M)
{
    extern __shared__ char smem[];
    const uint32_t smem_u32 = smem_to_u32(smem);
    const int tid = threadIdx.x;
    const int lane = tid & 31;
    const int wid = tid >> 5;
    const int wm = wid & 3;
    const int wn = wid >> 2;
    const int block_row = blockIdx.x * 128;

    float acc[2][8][4];
#pragma unroll
    for (int mt = 0; mt < 2; mt++)
#pragma unroll
        for (int nt = 0; nt < 8; nt++)
#pragma unroll
            for (int i = 0; i < 4; i++) acc[mt][nt][i] = 0.f;

    float4 areg[4], breg[4];

    auto gload = [&](int c) {
#pragma unroll
        for (int i = 0; i < 4; i++) {
            int s = tid + i * 256;
            int r = s >> 3, q = s & 7;
            int gr = block_row + r;
            areg[i] = (gr < M)
                ? *reinterpret_cast<const float4*>(A + (size_t)gr * F_IN + c * 32 + q * 4)
                : make_float4(0.f, 0.f, 0.f, 0.f);
            int kr = s >> 5, qb = s & 31;
            breg[i] = *reinterpret_cast<const float4*>(W + (size_t)(c * 32 + kr) * F_OUT + qb * 4);
        }
    };
    auto sstore = [&](int buf) {
        char* st = smem + buf * STAGE_SZ;
#pragma unroll
        for (int i = 0; i < 4; i++) {
            int s = tid + i * 256;
            int r = s >> 3, q = s & 7;
            uint2 hi, lo;
            split4(areg[i], hi, lo);
            *reinterpret_cast<uint2*>(st + AHI_OFF + r * A_ROW_B + q * 8) = hi;
            *reinterpret_cast<uint2*>(st + ALO_OFF + r * A_ROW_B + q * 8) = lo;
            int kr = s >> 5, qb = s & 31;
            split4(breg[i], hi, lo);
            *reinterpret_cast<uint2*>(st + BHI_OFF + kr * B_ROW_B + qb * 8) = hi;
            *reinterpret_cast<uint2*>(st + BLO_OFF + kr * B_ROW_B + qb * 8) = lo;
        }
    };

    const int a_row_in_tile = lane & 15;
    const int a_k_off = (lane >> 4) * 8;
    const int b_grp = lane >> 3;
    const int b_lr = lane & 7;
    const int b_k_in = (b_grp & 1) * 8 + b_lr;
    const int b_n_off = (b_grp >> 1) * 8;

    auto compute = [&](int buf) {
        const uint32_t st = smem_u32 + (uint32_t)buf * STAGE_SZ;
#pragma unroll
        for (int ks = 0; ks < 2; ks++) {
            uint32_t ah[2][4], al[2][4], bb[4][4];
#pragma unroll
            for (int mt = 0; mt < 2; mt++) {
                int row = wm * 32 + mt * 16 + a_row_in_tile;
                int col = ks * 16 + a_k_off;
                uint32_t ad = st + AHI_OFF + (uint32_t)row * A_ROW_B + (uint32_t)col * 2;
                LDSM_X4(ah[mt][0], ah[mt][1], ah[mt][2], ah[mt][3], ad);
                ad = st + ALO_OFF + (uint32_t)row * A_ROW_B + (uint32_t)col * 2;
                LDSM_X4(al[mt][0], al[mt][1], al[mt][2], al[mt][3], ad);
            }
#pragma unroll
            for (int g = 0; g < 4; g++) {
                int krow = ks * 16 + b_k_in;
                int ncol = wn * 64 + g * 16 + b_n_off;
                uint32_t bd = st + BHI_OFF + (uint32_t)krow * B_ROW_B + (uint32_t)ncol * 2;
                LDSM_X4_T(bb[g][0], bb[g][1], bb[g][2], bb[g][3], bd);
            }
#pragma unroll
            for (int mt = 0; mt < 2; mt++)
#pragma unroll
                for (int nt = 0; nt < 8; nt++) {
                    int g = nt >> 1, p = (nt & 1) * 2;
                    MMA_BF16(acc[mt][nt], ah[mt], bb[g][p], bb[g][p + 1]);
                    MMA_BF16(acc[mt][nt], al[mt], bb[g][p], bb[g][p + 1]);
                }
#pragma unroll
            for (int g = 0; g < 4; g++) {
                int krow = ks * 16 + b_k_in;
                int ncol = wn * 64 + g * 16 + b_n_off;
                uint32_t bd = st + BLO_OFF + (uint32_t)krow * B_ROW_B + (uint32_t)ncol * 2;
                LDSM_X4_T(bb[g][0], bb[g][1], bb[g][2], bb[g][3], bd);
            }
#pragma unroll
            for (int mt = 0; mt < 2; mt++)
#pragma unroll
                for (int nt = 0; nt < 8; nt++) {
                    int g = nt >> 1, p = (nt & 1) * 2;
                    MMA_BF16(acc[mt][nt], ah[mt], bb[g][p], bb[g][p + 1]);
                }
        }
    };

    gload(0);
    sstore(0);
    __syncthreads();
#pragma unroll
    for (int c = 0; c < 8; c++) {
        if (c < 7) gload(c + 1);
        compute(c & 1);
        if (c < 7) {
            sstore((c + 1) & 1);
            __syncthreads();
        }
    }

    // ---- epilogue: fp16 store ----
#pragma unroll
    for (int mt = 0; mt < 2; mt++) {
        int row0 = block_row + wm * 32 + mt * 16 + (lane >> 2);
#pragma unroll
        for (int nt = 0; nt < 8; nt++) {
            int col = wn * 64 + nt * 8 + (lane & 3) * 2;
            if (row0 < M)
                *reinterpret_cast<__half2*>(H + (size_t)row0 * F_OUT + col) =
                    __floats2half2_rn(acc[mt][nt][0], acc[mt][nt][1]);
            if (row0 + 8 < M)
                *reinterpret_cast<__half2*>(H + (size_t)(row0 + 8) * F_OUT + col) =
                    __floats2half2_rn(acc[mt][nt][2], acc[mt][nt][3]);
        }
    }
}

// ======================= CSR build: hist + scan + permute ===================
__global__ __launch_bounds__(256) void hist_kernel(const int* __restrict__ row, int E) {
    int e = blockIdx.x * 256 + threadIdx.x;
    if (e < E) atomicAdd(&g_cnt[row[e]], 1);
}

__device__ __forceinline__ int block_excl_scan(int v, int tid, int* total) {
    const unsigned full = 0xffffffffu;
    int lane = tid & 31, wid = tid >> 5;
    int x = v;
#pragma unroll
    for (int d = 1; d < 32; d <<= 1) {
        int y = __shfl_up_sync(full, x, d);
        if (lane >= d) x += y;
    }
    __shared__ int wsum[32];
    if (lane == 31) wsum[wid] = x;
    __syncthreads();
    if (wid == 0) {
        int s = wsum[lane];
#pragma unroll
        for (int d = 1; d < 32; d <<= 1) {
            int y = __shfl_up_sync(full, s, d);
            if (lane >= d) s += y;
        }
        wsum[lane] = s;
    }
    __syncthreads();
    int woff = (wid > 0) ? wsum[wid - 1] : 0;
    if (total) *total = wsum[31];
    return woff + x - v;
}

__global__ __launch_bounds__(1024) void scan1_kernel(int n, int nb) {
    int i = blockIdx.x * 1024 + threadIdx.x;
    int v = (i < n) ? g_cnt[i] : 0;
    int total;
    int excl = block_excl_scan(v, threadIdx.x, &total);
    if (i < n) g_offs[i] = excl;
    if (threadIdx.x == 0) g_bsum[blockIdx.x] = total;
}

__global__ __launch_bounds__(1024) void scan2_kernel(int nb) {
    int v = (threadIdx.x < nb) ? g_bsum[threadIdx.x] : 0;
    int excl = block_excl_scan(v, threadIdx.x, nullptr);
    if (threadIdx.x < nb) g_bsum[threadIdx.x] = excl;
}

__global__ __launch_bounds__(1024) void scan3_kernel(int n) {
    int i = blockIdx.x * 1024 + threadIdx.x;
    if (i < n) {
        int o = g_offs[i] + g_bsum[blockIdx.x];
        g_offs[i] = o;
        g_cursor[i] = o;
    }
}

__global__ __launch_bounds__(256) void permute_kernel(
    const int* __restrict__ row, const int* __restrict__ col,
    const float* __restrict__ val, int E)
{
    int e = blockIdx.x * 256 + threadIdx.x;
    if (e >= E) return;
    int r = row[e];
    int p = atomicAdd(&g_cursor[r], 1);
    g_sorted[p] = make_int2(col[e], __float_as_int(val[e]));
}

// ======================= Gather (fp16 h) + fused bias/relu ==================
// One warp per row; lane owns 4 contiguous features (8B fp16 load per edge).
__global__ __launch_bounds__(256) void gather_kernel(
    const __half* __restrict__ h, const float* __restrict__ b,
    float* __restrict__ out, int N)
{
    int row = (int)((blockIdx.x * 256u + threadIdx.x) >> 5);
    int lane = threadIdx.x & 31;
    if (row >= N) return;

    int start = g_offs[row];
    int deg   = g_cnt[row];

    float4 acc = make_float4(0.f, 0.f, 0.f, 0.f);
    const unsigned full = 0xffffffffu;

    for (int base = 0; base < deg; base += 32) {
        int nn = deg - base;
        if (nn > 32) nn = 32;
        int2 cv = make_int2(0, 0);
        if (lane < nn) cv = g_sorted[start + base + lane];
        for (int j = 0; j < nn; j++) {
            int   c = __shfl_sync(full, cv.x, j);
            float v = __int_as_float(__shfl_sync(full, cv.y, j));
            uint2 hv = *reinterpret_cast<const uint2*>(h + (size_t)c * F_OUT + lane * 4);
            float2 f01 = __half22float2(*reinterpret_cast<__half2*>(&hv.x));
            float2 f23 = __half22float2(*reinterpret_cast<__half2*>(&hv.y));
            acc.x = fmaf(v, f01.x, acc.x);
            acc.y = fmaf(v, f01.y, acc.y);
            acc.z = fmaf(v, f23.x, acc.z);
            acc.w = fmaf(v, f23.y, acc.w);
        }
    }

    const float4 bv = *reinterpret_cast<const float4*>(b + lane * 4);
    acc.x = fmaxf(acc.x + bv.x, 0.f);
    acc.y = fmaxf(acc.y + bv.y, 0.f);
    acc.z = fmaxf(acc.z + bv.z, 0.f);
    acc.w = fmaxf(acc.w + bv.w, 0.f);
    *reinterpret_cast<float4*>(out + (size_t)row * F_OUT + lane * 4) = acc;
}

// ---------------------------------------------------------------------------
extern "C" void kernel_launch(void* const* d_in, const int* in_sizes, int n_in,
                              void* d_out, int out_size)
{
    const float* x        = (const float*)d_in[0];
    const int*   adj_row  = (const int*)  d_in[1];
    const int*   adj_col  = (const int*)  d_in[2];
    const float* adj_vals = (const float*)d_in[3];
    const float* w        = (const float*)d_in[4];
    const float* b        = (const float*)d_in[5];
    float*       out      = (float*)d_out;

    const int fout = in_sizes[5];               // 128
    const int fin  = in_sizes[4] / fout;        // 256
    const int N    = in_sizes[0] / fin;         // 100000
    const int E    = in_sizes[1];               // 1600000

    __half* h;
    cudaGetSymbolAddress((void**)&h, g_h);
    int* cnt;
    cudaGetSymbolAddress((void**)&cnt, g_cnt);

    static cudaStream_t s1 = nullptr;
    static cudaEvent_t ev_root, ev_csr;
    if (!s1) {
        cudaStreamCreateWithFlags(&s1, cudaStreamNonBlocking);
        cudaEventCreateWithFlags(&ev_root, cudaEventDisableTiming);
        cudaEventCreateWithFlags(&ev_csr,  cudaEventDisableTiming);
        cudaFuncSetAttribute(gemm_mma_kernel, cudaFuncAttributeMaxDynamicSharedMemorySize, SMEM_TOTAL);
    }

    const int NB = (N + 1023) / 1024;

    // fork s1 off the capture stream
    cudaEventRecord(ev_root, 0);
    cudaStreamWaitEvent(s1, ev_root, 0);

    // --- s1: CSR build (hidden under GEMM) ---
    cudaMemsetAsync(cnt, 0, (size_t)N * sizeof(int), s1);
    hist_kernel<<<(E + 255) / 256, 256, 0, s1>>>(adj_row, E);
    scan1_kernel<<<NB, 1024, 0, s1>>>(N, NB);
    scan2_kernel<<<1, 1024, 0, s1>>>(NB);
    scan3_kernel<<<NB, 1024, 0, s1>>>(N);
    permute_kernel<<<(E + 255) / 256, 256, 0, s1>>>(adj_row, adj_col, adj_vals, E);
    cudaEventRecord(ev_csr, s1);

    // --- s0: full GEMM ---
    gemm_mma_kernel<<<(N + 127) / 128, 256, SMEM_TOTAL, 0>>>(x, w, h, N);

    // --- s0: gather (needs GEMM [in-stream] + CSR) ---
    cudaStreamWaitEvent(0, ev_csr, 0);
    gather_kernel<<<(int)(((long long)N * 32 + 255) / 256), 256, 0, 0>>>(h, b, out, N);
}

// round 7
// speedup vs baseline: 2.9945x; 1.2203x over previous
#include <cuda_runtime.h>
#include <cuda_fp16.h>
#include <cstdint>

// ---------------------------------------------------------------------------
// GraphConvolution: out = relu( SpMM_COO(adj, x @ w) + b )
//  s1: CSR build (hist/scan/permute)      [hidden under GEMM]
//  s0: fp16 single-product mma.sync GEMM -> h stored fp16
//  s0: gather (fp16 h, fp32 accum) + fused bias/relu     [waits CSR]
// ---------------------------------------------------------------------------

#define F_IN 256
#define F_OUT 128
#define MAX_N 100000
#define MAX_E 1600000

__device__ __half g_h[(size_t)MAX_N * F_OUT];
__device__ int   g_cnt[MAX_N];
__device__ int   g_offs[MAX_N];
__device__ int   g_cursor[MAX_N];
__device__ int   g_bsum[1024];
__device__ int2  g_sorted[MAX_E];

__device__ __forceinline__ uint32_t smem_to_u32(const void* p) {
    uint32_t a;
    asm("{ .reg .u64 t; cvta.to.shared.u64 t, %1; cvt.u32.u64 %0, t; }" : "=r"(a) : "l"(p));
    return a;
}

// ======================= fp16 GEMM (BM=128, BN=128, BK=32) ==================
// A tile: 128 rows x 32 k fp16, row stride 40 elems (80B)
// B tile: 32 k x 128 n fp16, row stride 136 elems (272B)
#define A_ROW_B   80
#define B_ROW_B   272
#define A_OFF     0
#define B_OFF     10240
#define STAGE_SZ  18944
#define SMEM_TOTAL (2 * STAGE_SZ)

#define LDSM_X4(r0, r1, r2, r3, addr) \
    asm volatile("ldmatrix.sync.aligned.m8n8.x4.shared.b16 {%0,%1,%2,%3}, [%4];" \
        : "=r"(r0), "=r"(r1), "=r"(r2), "=r"(r3) : "r"(addr))
#define LDSM_X4_T(r0, r1, r2, r3, addr) \
    asm volatile("ldmatrix.sync.aligned.m8n8.x4.trans.shared.b16 {%0,%1,%2,%3}, [%4];" \
        : "=r"(r0), "=r"(r1), "=r"(r2), "=r"(r3) : "r"(addr))
#define MMA_F16(d, a, b0, b1) \
    asm volatile("mma.sync.aligned.m16n8k16.row.col.f32.f16.f16.f32 " \
        "{%0,%1,%2,%3},{%4,%5,%6,%7},{%8,%9},{%0,%1,%2,%3};" \
        : "+f"((d)[0]), "+f"((d)[1]), "+f"((d)[2]), "+f"((d)[3]) \
        : "r"((a)[0]), "r"((a)[1]), "r"((a)[2]), "r"((a)[3]), "r"(b0), "r"(b1))

__device__ __forceinline__ uint2 cvt4(float4 v) {
    uint2 r;
    __half2 p0 = __floats2half2_rn(v.x, v.y);
    __half2 p1 = __floats2half2_rn(v.z, v.w);
    r.x = *reinterpret_cast<uint32_t*>(&p0);
    r.y = *reinterpret_cast<uint32_t*>(&p1);
    return r;
}

__global__ __launch_bounds__(256, 2) void gemm_fp16_kernel(
    const float* __restrict__ A,
    const float* __restrict__ W,
    __half* __restrict__ H,
    int M)
{
    extern __shared__ char smem[];
    const uint32_t smem_u32 = smem_to_u32(smem);
    const int tid = threadIdx.x;
    const int lane = tid & 31;
    const int wid = tid >> 5;
    const int wm = wid & 3;          // warp row -> rows wm*32..+32
    const int wn = wid >> 2;         // warp col -> cols wn*64..+64
    const int block_row = blockIdx.x * 128;

    float acc[2][8][4];
#pragma unroll
    for (int mt = 0; mt < 2; mt++)
#pragma unroll
        for (int nt = 0; nt < 8; nt++)
#pragma unroll
            for (int i = 0; i < 4; i++) acc[mt][nt][i] = 0.f;

    float4 areg[4], breg[4];

    auto gload = [&](int c) {
#pragma unroll
        for (int i = 0; i < 4; i++) {
            int s = tid + i * 256;
            int r = s >> 3, q = s & 7;
            int gr = block_row + r;
            areg[i] = (gr < M)
                ? *reinterpret_cast<const float4*>(A + (size_t)gr * F_IN + c * 32 + q * 4)
                : make_float4(0.f, 0.f, 0.f, 0.f);
            int kr = s >> 5, qb = s & 31;
            breg[i] = *reinterpret_cast<const float4*>(W + (size_t)(c * 32 + kr) * F_OUT + qb * 4);
        }
    };
    auto sstore = [&](int buf) {
        char* st = smem + buf * STAGE_SZ;
#pragma unroll
        for (int i = 0; i < 4; i++) {
            int s = tid + i * 256;
            int r = s >> 3, q = s & 7;
            *reinterpret_cast<uint2*>(st + A_OFF + r * A_ROW_B + q * 8) = cvt4(areg[i]);
            int kr = s >> 5, qb = s & 31;
            *reinterpret_cast<uint2*>(st + B_OFF + kr * B_ROW_B + qb * 8) = cvt4(breg[i]);
        }
    };

    const int a_row_in_tile = lane & 15;
    const int a_k_off = (lane >> 4) * 8;
    const int b_grp = lane >> 3;
    const int b_lr = lane & 7;
    const int b_k_in = (b_grp & 1) * 8 + b_lr;
    const int b_n_off = (b_grp >> 1) * 8;

    auto compute = [&](int buf) {
        const uint32_t st = smem_u32 + (uint32_t)buf * STAGE_SZ;
#pragma unroll
        for (int ks = 0; ks < 2; ks++) {
            uint32_t ah[2][4], bb[4][4];
#pragma unroll
            for (int mt = 0; mt < 2; mt++) {
                int row = wm * 32 + mt * 16 + a_row_in_tile;
                int col = ks * 16 + a_k_off;
                uint32_t ad = st + A_OFF + (uint32_t)row * A_ROW_B + (uint32_t)col * 2;
                LDSM_X4(ah[mt][0], ah[mt][1], ah[mt][2], ah[mt][3], ad);
            }
#pragma unroll
            for (int g = 0; g < 4; g++) {
                int krow = ks * 16 + b_k_in;
                int ncol = wn * 64 + g * 16 + b_n_off;
                uint32_t bd = st + B_OFF + (uint32_t)krow * B_ROW_B + (uint32_t)ncol * 2;
                LDSM_X4_T(bb[g][0], bb[g][1], bb[g][2], bb[g][3], bd);
            }
#pragma unroll
            for (int mt = 0; mt < 2; mt++)
#pragma unroll
                for (int nt = 0; nt < 8; nt++) {
                    int g = nt >> 1, p = (nt & 1) * 2;
                    MMA_F16(acc[mt][nt], ah[mt], bb[g][p], bb[g][p + 1]);
                }
        }
    };

    gload(0);
    sstore(0);
    __syncthreads();
#pragma unroll
    for (int c = 0; c < 8; c++) {
        if (c < 7) gload(c + 1);
        compute(c & 1);
        if (c < 7) {
            sstore((c + 1) & 1);
            __syncthreads();
        }
    }

    // ---- epilogue: fp16 store ----
#pragma unroll
    for (int mt = 0; mt < 2; mt++) {
        int row0 = block_row + wm * 32 + mt * 16 + (lane >> 2);
#pragma unroll
        for (int nt = 0; nt < 8; nt++) {
            int col = wn * 64 + nt * 8 + (lane & 3) * 2;
            if (row0 < M)
                *reinterpret_cast<__half2*>(H + (size_t)row0 * F_OUT + col) =
                    __floats2half2_rn(acc[mt][nt][0], acc[mt][nt][1]);
            if (row0 + 8 < M)
                *reinterpret_cast<__half2*>(H + (size_t)(row0 + 8) * F_OUT + col) =
                    __floats2half2_rn(acc[mt][nt][2], acc[mt][nt][3]);
        }
    }
}

// ======================= CSR build: hist + scan + permute ===================
__global__ __launch_bounds__(256) void hist_kernel(const int* __restrict__ row, int E) {
    int e = blockIdx.x * 256 + threadIdx.x;
    if (e < E) atomicAdd(&g_cnt[row[e]], 1);
}

__device__ __forceinline__ int block_excl_scan(int v, int tid, int* total) {
    const unsigned full = 0xffffffffu;
    int lane = tid & 31, wid = tid >> 5;
    int x = v;
#pragma unroll
    for (int d = 1; d < 32; d <<= 1) {
        int y = __shfl_up_sync(full, x, d);
        if (lane >= d) x += y;
    }
    __shared__ int wsum[32];
    if (lane == 31) wsum[wid] = x;
    __syncthreads();
    if (wid == 0) {
        int s = wsum[lane];
#pragma unroll
        for (int d = 1; d < 32; d <<= 1) {
            int y = __shfl_up_sync(full, s, d);
            if (lane >= d) s += y;
        }
        wsum[lane] = s;
    }
    __syncthreads();
    int woff = (wid > 0) ? wsum[wid - 1] : 0;
    if (total) *total = wsum[31];
    return woff + x - v;
}

__global__ __launch_bounds__(1024) void scan1_kernel(int n, int nb) {
    int i = blockIdx.x * 1024 + threadIdx.x;
    int v = (i < n) ? g_cnt[i] : 0;
    int total;
    int excl = block_excl_scan(v, threadIdx.x, &total);
    if (i < n) g_offs[i] = excl;
    if (threadIdx.x == 0) g_bsum[blockIdx.x] = total;
}

// merged scan2+scan3: each block redundantly reduces bsum[0..bid) for its base
__global__ __launch_bounds__(1024) void scan23_kernel(int n, int nb) {
    int tid = threadIdx.x;
    int v = (tid < blockIdx.x) ? g_bsum[tid] : 0;   // nb <= 1024
    int base;
    block_excl_scan(v, tid, &base);                  // base = sum over [0, bid)
    int i = blockIdx.x * 1024 + tid;
    if (i < n) {
        int o = g_offs[i] + base;
        g_offs[i] = o;
        g_cursor[i] = o;
    }
}

__global__ __launch_bounds__(256) void permute_kernel(
    const int* __restrict__ row, const int* __restrict__ col,
    const float* __restrict__ val, int E)
{
    int e = blockIdx.x * 256 + threadIdx.x;
    if (e >= E) return;
    int r = row[e];
    int p = atomicAdd(&g_cursor[r], 1);
    g_sorted[p] = make_int2(col[e], __float_as_int(val[e]));
}

// ======================= Gather (fp16 h) + fused bias/relu ==================
__global__ __launch_bounds__(256) void gather_kernel(
    const __half* __restrict__ h, const float* __restrict__ b,
    float* __restrict__ out, int N)
{
    int row = (int)((blockIdx.x * 256u + threadIdx.x) >> 5);
    int lane = threadIdx.x & 31;
    if (row >= N) return;

    int start = g_offs[row];
    int deg   = g_cnt[row];

    float4 acc = make_float4(0.f, 0.f, 0.f, 0.f);
    const unsigned full = 0xffffffffu;

    for (int base = 0; base < deg; base += 32) {
        int nn = deg - base;
        if (nn > 32) nn = 32;
        int2 cv = make_int2(0, 0);
        if (lane < nn) cv = g_sorted[start + base + lane];
        for (int j = 0; j < nn; j++) {
            int   c = __shfl_sync(full, cv.x, j);
            float v = __int_as_float(__shfl_sync(full, cv.y, j));
            uint2 hv = *reinterpret_cast<const uint2*>(h + (size_t)c * F_OUT + lane * 4);
            float2 f01 = __half22float2(*reinterpret_cast<__half2*>(&hv.x));
            float2 f23 = __half22float2(*reinterpret_cast<__half2*>(&hv.y));
            acc.x = fmaf(v, f01.x, acc.x);
            acc.y = fmaf(v, f01.y, acc.y);
            acc.z = fmaf(v, f23.x, acc.z);
            acc.w = fmaf(v, f23.y, acc.w);
        }
    }

    const float4 bv = *reinterpret_cast<const float4*>(b + lane * 4);
    acc.x = fmaxf(acc.x + bv.x, 0.f);
    acc.y = fmaxf(acc.y + bv.y, 0.f);
    acc.z = fmaxf(acc.z + bv.z, 0.f);
    acc.w = fmaxf(acc.w + bv.w, 0.f);
    *reinterpret_cast<float4*>(out + (size_t)row * F_OUT + lane * 4) = acc;
}

// ---------------------------------------------------------------------------
extern "C" void kernel_launch(void* const* d_in, const int* in_sizes, int n_in,
                              void* d_out, int out_size)
{
    const float* x        = (const float*)d_in[0];
    const int*   adj_row  = (const int*)  d_in[1];
    const int*   adj_col  = (const int*)  d_in[2];
    const float* adj_vals = (const float*)d_in[3];
    const float* w        = (const float*)d_in[4];
    const float* b        = (const float*)d_in[5];
    float*       out      = (float*)d_out;

    const int fout = in_sizes[5];               // 128
    const int fin  = in_sizes[4] / fout;        // 256
    const int N    = in_sizes[0] / fin;         // 100000
    const int E    = in_sizes[1];               // 1600000

    __half* h;
    cudaGetSymbolAddress((void**)&h, g_h);
    int* cnt;
    cudaGetSymbolAddress((void**)&cnt, g_cnt);

    static cudaStream_t s1 = nullptr;
    static cudaEvent_t ev_root, ev_csr;
    if (!s1) {
        cudaStreamCreateWithFlags(&s1, cudaStreamNonBlocking);
        cudaEventCreateWithFlags(&ev_root, cudaEventDisableTiming);
        cudaEventCreateWithFlags(&ev_csr,  cudaEventDisableTiming);
        cudaFuncSetAttribute(gemm_fp16_kernel, cudaFuncAttributeMaxDynamicSharedMemorySize, SMEM_TOTAL);
    }

    const int NB = (N + 1023) / 1024;

    // fork s1 off the capture stream
    cudaEventRecord(ev_root, 0);
    cudaStreamWaitEvent(s1, ev_root, 0);

    // --- s1: CSR build (hidden under GEMM) ---
    cudaMemsetAsync(cnt, 0, (size_t)N * sizeof(int), s1);
    hist_kernel<<<(E + 255) / 256, 256, 0, s1>>>(adj_row, E);
    scan1_kernel<<<NB, 1024, 0, s1>>>(N, NB);
    scan23_kernel<<<NB, 1024, 0, s1>>>(N, NB);
    permute_kernel<<<(E + 255) / 256, 256, 0, s1>>>(adj_row, adj_col, adj_vals, E);
    cudaEventRecord(ev_csr, s1);

    // --- s0: fp16 GEMM ---
    gemm_fp16_kernel<<<(N + 127) / 128, 256, SMEM_TOTAL, 0>>>(x, w, h, N);

    // --- s0: gather (needs GEMM [in-stream] + CSR) ---
    cudaStreamWaitEvent(0, ev_csr, 0);
    gather_kernel<<<(int)(((long long)N * 32 + 255) / 256), 256, 0, 0>>>(h, b, out, N);
}

// round 8
// speedup vs baseline: 3.0561x; 1.0206x over previous
#include <cuda_runtime.h>
#include <cuda_fp16.h>
#include <cstdint>

// ---------------------------------------------------------------------------
// GraphConvolution: out = relu( SpMM_COO(adj, x @ w) + b )
//  s1: CSR build: hist(+rank capture) -> scan -> atomic-free permute [|| GEMM]
//  s0: fp16 single-product mma.sync GEMM -> h stored fp16
//  s0: gather (fp16 h, fp32 accum) + fused bias/relu     [waits CSR]
// ---------------------------------------------------------------------------

#define F_IN 256
#define F_OUT 128
#define MAX_N 100000
#define MAX_E 1600000

__device__ __half g_h[(size_t)MAX_N * F_OUT];
__device__ int   g_cnt[MAX_N];
__device__ int   g_offs[MAX_N];
__device__ int   g_rank[MAX_E];
__device__ int   g_bsum[1024];
__device__ int2  g_sorted[MAX_E];

__device__ __forceinline__ uint32_t smem_to_u32(const void* p) {
    uint32_t a;
    asm("{ .reg .u64 t; cvta.to.shared.u64 t, %1; cvt.u32.u64 %0, t; }" : "=r"(a) : "l"(p));
    return a;
}

// ======================= fp16 GEMM (BM=128, BN=128, BK=32) ==================
#define A_ROW_B   80
#define B_ROW_B   272
#define A_OFF     0
#define B_OFF     10240
#define STAGE_SZ  18944
#define SMEM_TOTAL (2 * STAGE_SZ)

#define LDSM_X4(r0, r1, r2, r3, addr) \
    asm volatile("ldmatrix.sync.aligned.m8n8.x4.shared.b16 {%0,%1,%2,%3}, [%4];" \
        : "=r"(r0), "=r"(r1), "=r"(r2), "=r"(r3) : "r"(addr))
#define LDSM_X4_T(r0, r1, r2, r3, addr) \
    asm volatile("ldmatrix.sync.aligned.m8n8.x4.trans.shared.b16 {%0,%1,%2,%3}, [%4];" \
        : "=r"(r0), "=r"(r1), "=r"(r2), "=r"(r3) : "r"(addr))
#define MMA_F16(d, a, b0, b1) \
    asm volatile("mma.sync.aligned.m16n8k16.row.col.f32.f16.f16.f32 " \
        "{%0,%1,%2,%3},{%4,%5,%6,%7},{%8,%9},{%0,%1,%2,%3};" \
        : "+f"((d)[0]), "+f"((d)[1]), "+f"((d)[2]), "+f"((d)[3]) \
        : "r"((a)[0]), "r"((a)[1]), "r"((a)[2]), "r"((a)[3]), "r"(b0), "r"(b1))

__device__ __forceinline__ uint2 cvt4(float4 v) {
    uint2 r;
    __half2 p0 = __floats2half2_rn(v.x, v.y);
    __half2 p1 = __floats2half2_rn(v.z, v.w);
    r.x = *reinterpret_cast<uint32_t*>(&p0);
    r.y = *reinterpret_cast<uint32_t*>(&p1);
    return r;
}

__global__ __launch_bounds__(256, 2) void gemm_fp16_kernel(
    const float* __restrict__ A,
    const float* __restrict__ W,
    __half* __restrict__ H,
    int M)
{
    extern __shared__ char smem[];
    const uint32_t smem_u32 = smem_to_u32(smem);
    const int tid = threadIdx.x;
    const int lane = tid & 31;
    const int wid = tid >> 5;
    const int wm = wid & 3;
    const int wn = wid >> 2;
    const int block_row = blockIdx.x * 128;

    float acc[2][8][4];
#pragma unroll
    for (int mt = 0; mt < 2; mt++)
#pragma unroll
        for (int nt = 0; nt < 8; nt++)
#pragma unroll
            for (int i = 0; i < 4; i++) acc[mt][nt][i] = 0.f;

    float4 areg[4], breg[4];

    auto gload = [&](int c) {
#pragma unroll
        for (int i = 0; i < 4; i++) {
            int s = tid + i * 256;
            int r = s >> 3, q = s & 7;
            int gr = block_row + r;
            areg[i] = (gr < M)
                ? *reinterpret_cast<const float4*>(A + (size_t)gr * F_IN + c * 32 + q * 4)
                : make_float4(0.f, 0.f, 0.f, 0.f);
            int kr = s >> 5, qb = s & 31;
            breg[i] = *reinterpret_cast<const float4*>(W + (size_t)(c * 32 + kr) * F_OUT + qb * 4);
        }
    };
    auto sstore = [&](int buf) {
        char* st = smem + buf * STAGE_SZ;
#pragma unroll
        for (int i = 0; i < 4; i++) {
            int s = tid + i * 256;
            int r = s >> 3, q = s & 7;
            *reinterpret_cast<uint2*>(st + A_OFF + r * A_ROW_B + q * 8) = cvt4(areg[i]);
            int kr = s >> 5, qb = s & 31;
            *reinterpret_cast<uint2*>(st + B_OFF + kr * B_ROW_B + qb * 8) = cvt4(breg[i]);
        }
    };

    const int a_row_in_tile = lane & 15;
    const int a_k_off = (lane >> 4) * 8;
    const int b_grp = lane >> 3;
    const int b_lr = lane & 7;
    const int b_k_in = (b_grp & 1) * 8 + b_lr;
    const int b_n_off = (b_grp >> 1) * 8;

    auto compute = [&](int buf) {
        const uint32_t st = smem_u32 + (uint32_t)buf * STAGE_SZ;
#pragma unroll
        for (int ks = 0; ks < 2; ks++) {
            uint32_t ah[2][4], bb[4][4];
#pragma unroll
            for (int mt = 0; mt < 2; mt++) {
                int row = wm * 32 + mt * 16 + a_row_in_tile;
                int col = ks * 16 + a_k_off;
                uint32_t ad = st + A_OFF + (uint32_t)row * A_ROW_B + (uint32_t)col * 2;
                LDSM_X4(ah[mt][0], ah[mt][1], ah[mt][2], ah[mt][3], ad);
            }
#pragma unroll
            for (int g = 0; g < 4; g++) {
                int krow = ks * 16 + b_k_in;
                int ncol = wn * 64 + g * 16 + b_n_off;
                uint32_t bd = st + B_OFF + (uint32_t)krow * B_ROW_B + (uint32_t)ncol * 2;
                LDSM_X4_T(bb[g][0], bb[g][1], bb[g][2], bb[g][3], bd);
            }
#pragma unroll
            for (int mt = 0; mt < 2; mt++)
#pragma unroll
                for (int nt = 0; nt < 8; nt++) {
                    int g = nt >> 1, p = (nt & 1) * 2;
                    MMA_F16(acc[mt][nt], ah[mt], bb[g][p], bb[g][p + 1]);
                }
        }
    };

    gload(0);
    sstore(0);
    __syncthreads();
#pragma unroll
    for (int c = 0; c < 8; c++) {
        if (c < 7) gload(c + 1);
        compute(c & 1);
        if (c < 7) {
            sstore((c + 1) & 1);
            __syncthreads();
        }
    }

#pragma unroll
    for (int mt = 0; mt < 2; mt++) {
        int row0 = block_row + wm * 32 + mt * 16 + (lane >> 2);
#pragma unroll
        for (int nt = 0; nt < 8; nt++) {
            int col = wn * 64 + nt * 8 + (lane & 3) * 2;
            if (row0 < M)
                *reinterpret_cast<__half2*>(H + (size_t)row0 * F_OUT + col) =
                    __floats2half2_rn(acc[mt][nt][0], acc[mt][nt][1]);
            if (row0 + 8 < M)
                *reinterpret_cast<__half2*>(H + (size_t)(row0 + 8) * F_OUT + col) =
                    __floats2half2_rn(acc[mt][nt][2], acc[mt][nt][3]);
        }
    }
}

// ======================= CSR build ==========================================
// hist: count + capture within-row rank (atomicAdd return value)
__global__ __launch_bounds__(256) void hist_kernel(const int* __restrict__ row, int E) {
    int e = blockIdx.x * 256 + threadIdx.x;
    if (e < E) g_rank[e] = atomicAdd(&g_cnt[row[e]], 1);
}

__device__ __forceinline__ int block_excl_scan(int v, int tid, int* total) {
    const unsigned full = 0xffffffffu;
    int lane = tid & 31, wid = tid >> 5;
    int x = v;
#pragma unroll
    for (int d = 1; d < 32; d <<= 1) {
        int y = __shfl_up_sync(full, x, d);
        if (lane >= d) x += y;
    }
    __shared__ int wsum[32];
    if (lane == 31) wsum[wid] = x;
    __syncthreads();
    if (wid == 0) {
        int s = wsum[lane];
#pragma unroll
        for (int d = 1; d < 32; d <<= 1) {
            int y = __shfl_up_sync(full, s, d);
            if (lane >= d) s += y;
        }
        wsum[lane] = s;
    }
    __syncthreads();
    int woff = (wid > 0) ? wsum[wid - 1] : 0;
    if (total) *total = wsum[31];
    return woff + x - v;
}

__global__ __launch_bounds__(1024) void scan1_kernel(int n, int nb) {
    int i = blockIdx.x * 1024 + threadIdx.x;
    int v = (i < n) ? g_cnt[i] : 0;
    int total;
    int excl = block_excl_scan(v, threadIdx.x, &total);
    if (i < n) g_offs[i] = excl;
    if (threadIdx.x == 0) g_bsum[blockIdx.x] = total;
}

__global__ __launch_bounds__(1024) void scan23_kernel(int n, int nb) {
    int tid = threadIdx.x;
    int v = (tid < blockIdx.x) ? g_bsum[tid] : 0;   // nb <= 1024
    int base;
    block_excl_scan(v, tid, &base);                  // sum over [0, bid)
    int i = blockIdx.x * 1024 + tid;
    if (i < n) g_offs[i] += base;
}

// atomic-free permute: p = offs[row] + rank
__global__ __launch_bounds__(256) void permute_kernel(
    const int* __restrict__ row, const int* __restrict__ col,
    const float* __restrict__ val, int E)
{
    int e = blockIdx.x * 256 + threadIdx.x;
    if (e >= E) return;
    int p = g_offs[row[e]] + g_rank[e];
    g_sorted[p] = make_int2(col[e], __float_as_int(val[e]));
}

// ======================= Gather (fp16 h) + fused bias/relu ==================
__global__ __launch_bounds__(256) void gather_kernel(
    const __half* __restrict__ h, const float* __restrict__ b,
    float* __restrict__ out, int N)
{
    int row = (int)((blockIdx.x * 256u + threadIdx.x) >> 5);
    int lane = threadIdx.x & 31;
    if (row >= N) return;

    int start = g_offs[row];
    int deg   = g_cnt[row];

    float4 acc = make_float4(0.f, 0.f, 0.f, 0.f);
    const unsigned full = 0xffffffffu;

    for (int base = 0; base < deg; base += 32) {
        int nn = deg - base;
        if (nn > 32) nn = 32;
        int2 cv = make_int2(0, 0);
        if (lane < nn) cv = g_sorted[start + base + lane];
        int j = 0;
        for (; j + 2 <= nn; j += 2) {
            int   c0 = __shfl_sync(full, cv.x, j);
            float v0 = __int_as_float(__shfl_sync(full, cv.y, j));
            int   c1 = __shfl_sync(full, cv.x, j + 1);
            float v1 = __int_as_float(__shfl_sync(full, cv.y, j + 1));
            uint2 h0 = *reinterpret_cast<const uint2*>(h + (size_t)c0 * F_OUT + lane * 4);
            uint2 h1 = *reinterpret_cast<const uint2*>(h + (size_t)c1 * F_OUT + lane * 4);
            float2 a01 = __half22float2(*reinterpret_cast<__half2*>(&h0.x));
            float2 a23 = __half22float2(*reinterpret_cast<__half2*>(&h0.y));
            float2 b01 = __half22float2(*reinterpret_cast<__half2*>(&h1.x));
            float2 b23 = __half22float2(*reinterpret_cast<__half2*>(&h1.y));
            acc.x = fmaf(v0, a01.x, acc.x);
            acc.y = fmaf(v0, a01.y, acc.y);
            acc.z = fmaf(v0, a23.x, acc.z);
            acc.w = fmaf(v0, a23.y, acc.w);
            acc.x = fmaf(v1, b01.x, acc.x);
            acc.y = fmaf(v1, b01.y, acc.y);
            acc.z = fmaf(v1, b23.x, acc.z);
            acc.w = fmaf(v1, b23.y, acc.w);
        }
        if (j < nn) {
            int   c = __shfl_sync(full, cv.x, j);
            float v = __int_as_float(__shfl_sync(full, cv.y, j));
            uint2 hv = *reinterpret_cast<const uint2*>(h + (size_t)c * F_OUT + lane * 4);
            float2 f01 = __half22float2(*reinterpret_cast<__half2*>(&hv.x));
            float2 f23 = __half22float2(*reinterpret_cast<__half2*>(&hv.y));
            acc.x = fmaf(v, f01.x, acc.x);
            acc.y = fmaf(v, f01.y, acc.y);
            acc.z = fmaf(v, f23.x, acc.z);
            acc.w = fmaf(v, f23.y, acc.w);
        }
    }

    const float4 bv = *reinterpret_cast<const float4*>(b + lane * 4);
    acc.x = fmaxf(acc.x + bv.x, 0.f);
    acc.y = fmaxf(acc.y + bv.y, 0.f);
    acc.z = fmaxf(acc.z + bv.z, 0.f);
    acc.w = fmaxf(acc.w + bv.w, 0.f);
    *reinterpret_cast<float4*>(out + (size_t)row * F_OUT + lane * 4) = acc;
}

// ---------------------------------------------------------------------------
extern "C" void kernel_launch(void* const* d_in, const int* in_sizes, int n_in,
                              void* d_out, int out_size)
{
    const float* x        = (const float*)d_in[0];
    const int*   adj_row  = (const int*)  d_in[1];
    const int*   adj_col  = (const int*)  d_in[2];
    const float* adj_vals = (const float*)d_in[3];
    const float* w        = (const float*)d_in[4];
    const float* b        = (const float*)d_in[5];
    float*       out      = (float*)d_out;

    const int fout = in_sizes[5];               // 128
    const int fin  = in_sizes[4] / fout;        // 256
    const int N    = in_sizes[0] / fin;         // 100000
    const int E    = in_sizes[1];               // 1600000

    __half* h;
    cudaGetSymbolAddress((void**)&h, g_h);
    int* cnt;
    cudaGetSymbolAddress((void**)&cnt, g_cnt);

    static cudaStream_t s1 = nullptr;
    static cudaEvent_t ev_root, ev_csr;
    if (!s1) {
        cudaStreamCreateWithFlags(&s1, cudaStreamNonBlocking);
        cudaEventCreateWithFlags(&ev_root, cudaEventDisableTiming);
        cudaEventCreateWithFlags(&ev_csr,  cudaEventDisableTiming);
        cudaFuncSetAttribute(gemm_fp16_kernel, cudaFuncAttributeMaxDynamicSharedMemorySize, SMEM_TOTAL);
    }

    const int NB = (N + 1023) / 1024;

    // fork s1 off the capture stream
    cudaEventRecord(ev_root, 0);
    cudaStreamWaitEvent(s1, ev_root, 0);

    // --- s1: CSR build (hidden under GEMM) ---
    cudaMemsetAsync(cnt, 0, (size_t)N * sizeof(int), s1);
    hist_kernel<<<(E + 255) / 256, 256, 0, s1>>>(adj_row, E);
    scan1_kernel<<<NB, 1024, 0, s1>>>(N, NB);
    scan23_kernel<<<NB, 1024, 0, s1>>>(N, NB);
    permute_kernel<<<(E + 255) / 256, 256, 0, s1>>>(adj_row, adj_col, adj_vals, E);
    cudaEventRecord(ev_csr, s1);

    // --- s0: fp16 GEMM ---
    gemm_fp16_kernel<<<(N + 127) / 128, 256, SMEM_TOTAL, 0>>>(x, w, h, N);

    // --- s0: gather (needs GEMM [in-stream] + CSR) ---
    cudaStreamWaitEvent(0, ev_csr, 0);
    gather_kernel<<<(int)(((long long)N * 32 + 255) / 256), 256, 0, 0>>>(h, b, out, N);
}